// round 12
// baseline (speedup 1.0000x reference)
#include <cuda_runtime.h>
#include <cuda_bf16.h>
#include <cuda_fp16.h>
#include <math.h>
#include <stdint.h>

// ---------------- problem constants ----------------
#define NN 4096
#define DD 256
#define HH 8
#define HD 32
#define EE 65536
#define NWORDS 128
// (1/sqrt(32)) * log2(e): folded into Q so softmax weight = exp2(S)
#define QSCALE 0.25503486f
#define NSPLIT 2
#define TILES_PER_SPLIT 16

// ---------------- scratch globals (no allocs allowed) ----------------
__device__ uint32_t g_adj[NN * NWORDS];
__device__ uint32_t g_mask[NN * NWORDS];
__device__ __nv_bfloat16 g_xb[NN * DD];
__device__ __nv_bfloat16 g_Wb[4 * DD * DD];   // Wq, Wk, Wv, Wo (bf16)
__device__ __half g_Qh[NN * DD];              // fp16, pre-scaled by QSCALE
__device__ __half g_Kh[NN * DD];
__device__ __half g_Vh[NN * DD];
__device__ __nv_bfloat16 g_attb[NN * DD];     // attention output (bf16)
__device__ float g_tmp[NN * DD];
__device__ float g_pO[NSPLIT * NN * DD];      // split-KV partial O (unnormalized)
__device__ float g_pl[NSPLIT * HH * NN];      // split-KV partial row sums

// ---------------- PTX helpers ----------------
__device__ __forceinline__ uint32_t smem_u32(const void* p) {
    uint32_t a;
    asm("{ .reg .u64 t; cvta.to.shared.u64 t, %1; cvt.u32.u64 %0, t; }"
        : "=r"(a) : "l"(p));
    return a;
}
__device__ __forceinline__ uint32_t pack_bf16x2(float lo, float hi) {
    uint32_t r;
    asm("cvt.rn.bf16x2.f32 %0, %1, %2;" : "=r"(r) : "f"(hi), "f"(lo));
    return r;
}
__device__ __forceinline__ uint32_t pack_f16x2(float lo, float hi) {
    uint32_t r;
    asm("cvt.rn.f16x2.f32 %0, %1, %2;" : "=r"(r) : "f"(hi), "f"(lo));
    return r;
}
__device__ __forceinline__ uint32_t ex2_f16x2(uint32_t x) {
    uint32_t y;
    asm("ex2.approx.f16x2 %0, %1;" : "=r"(y) : "r"(x));
    return y;
}
__device__ __forceinline__ uint32_t hadd2(uint32_t a, uint32_t b) {
    uint32_t d;
    asm("add.rn.f16x2 %0, %1, %2;" : "=r"(d) : "r"(a), "r"(b));
    return d;
}
__device__ __forceinline__ uint32_t prmt(uint32_t a, uint32_t b, uint32_t sel) {
    uint32_t d;
    asm("prmt.b32 %0, %1, %2, %3;" : "=r"(d) : "r"(a), "r"(b), "r"(sel));
    return d;
}
__device__ __forceinline__ float2 h2_to_f2(uint32_t u) {
    __half2 h = *reinterpret_cast<__half2*>(&u);
    return __half22float2(h);
}
__device__ __forceinline__ void ldsm_x4(uint32_t* r, uint32_t addr) {
    asm volatile("ldmatrix.sync.aligned.m8n8.x4.shared.b16 {%0,%1,%2,%3}, [%4];"
        : "=r"(r[0]), "=r"(r[1]), "=r"(r[2]), "=r"(r[3]) : "r"(addr));
}
__device__ __forceinline__ void ldsm_x4_t(uint32_t* r, uint32_t addr) {
    asm volatile("ldmatrix.sync.aligned.m8n8.x4.trans.shared.b16 {%0,%1,%2,%3}, [%4];"
        : "=r"(r[0]), "=r"(r[1]), "=r"(r[2]), "=r"(r[3]) : "r"(addr));
}
__device__ __forceinline__ void mma_bf16(float* c, const uint32_t* a, const uint32_t* b) {
    asm volatile(
        "mma.sync.aligned.m16n8k16.row.col.f32.bf16.bf16.f32 "
        "{%0,%1,%2,%3}, {%4,%5,%6,%7}, {%8,%9}, {%0,%1,%2,%3};"
        : "+f"(c[0]), "+f"(c[1]), "+f"(c[2]), "+f"(c[3])
        : "r"(a[0]), "r"(a[1]), "r"(a[2]), "r"(a[3]), "r"(b[0]), "r"(b[1]));
}
// fp16 in, fp16 accumulate
__device__ __forceinline__ void mma_h(uint32_t* d, const uint32_t* a, const uint32_t* b) {
    asm volatile(
        "mma.sync.aligned.m16n8k16.row.col.f16.f16.f16.f16 "
        "{%0,%1}, {%2,%3,%4,%5}, {%6,%7}, {%0,%1};"
        : "+r"(d[0]), "+r"(d[1])
        : "r"(a[0]), "r"(a[1]), "r"(a[2]), "r"(a[3]), "r"(b[0]), "r"(b[1]));
}
__device__ __forceinline__ void cp16(uint32_t dst, const void* src) {
    asm volatile("cp.async.cg.shared.global [%0], [%1], 16;" :: "r"(dst), "l"(src));
}
#define CP_COMMIT() asm volatile("cp.async.commit_group;" ::: "memory")
#define CP_WAIT(n)  asm volatile("cp.async.wait_group %0;" :: "n"(n) : "memory")

// ================= K1: bf16 casts  ∥  adjacency init (one launch) =========
__global__ void __launch_bounds__(256) k1_kernel(const float* __restrict__ x,
                                                 const float* __restrict__ Wq,
                                                 const float* __restrict__ Wk,
                                                 const float* __restrict__ Wv,
                                                 const float* __restrict__ Wo) {
    int b = blockIdx.x;
    if (b < 1280) {
        int i = (b * 256 + threadIdx.x) * 4;
        const float* src;
        __nv_bfloat16* dst;
        if (i < NN * DD) {
            src = x + i; dst = g_xb + i;
        } else {
            int j = i - NN * DD;
            int w = j >> 16;
            int o = j & 65535;
            src = ((w == 0) ? Wq : (w == 1) ? Wk : (w == 2) ? Wv : Wo) + o;
            dst = g_Wb + w * (DD * DD) + o;
        }
        float4 v = *(const float4*)src;
        *(uint2*)dst = make_uint2(pack_bf16x2(v.x, v.y), pack_bf16x2(v.z, v.w));
    } else {
        int idx = (b - 1280) * 256 + threadIdx.x;
        int n = idx >> 7, w = idx & 127;
        uint32_t v = 0;
        if (w == (n >> 5)) v = 1u << (n & 31);
        g_adj[idx] = v;
    }
}

// ================= bf16 tensor-core GEMM core =================
template <int MODE>
__device__ __forceinline__ void gemm_core(const __nv_bfloat16* __restrict__ A,
                                          const __nv_bfloat16* __restrict__ W,
                                          const float* __restrict__ bias,
                                          void* __restrict__ Cv, float scale) {
    __shared__ __nv_bfloat16 sA[2][64 * 40];
    __shared__ __nv_bfloat16 sB[2][32 * 136];

    const int tid = threadIdx.x;
    const int wid = tid >> 5;
    const int lane = tid & 31;
    const int m0 = blockIdx.y * 64;
    const int n0 = blockIdx.x * 128;

    const uint32_t aA = smem_u32(sA);
    const uint32_t aB = smem_u32(sB);
    const char* Abase = (const char*)A + (size_t)m0 * (DD * 2);
    const char* Bbase = (const char*)W + (size_t)n0 * 2;

    {
#pragma unroll
        for (int j = 0; j < 2; j++) {
            int t = tid + j * 128;
            int r = t >> 2, c = t & 3;
            cp16(aA + r * 80 + c * 16, Abase + (size_t)r * 512 + c * 16);
        }
#pragma unroll
        for (int j = 0; j < 4; j++) {
            int t = tid + j * 128;
            int r = t >> 4, c = t & 15;
            cp16(aB + r * 272 + c * 16, Bbase + (size_t)r * 512 + c * 16);
        }
        CP_COMMIT();
    }

    float acc[16][4];
#pragma unroll
    for (int j = 0; j < 16; j++)
        acc[j][0] = acc[j][1] = acc[j][2] = acc[j][3] = 0.f;

    const int m = lane >> 3, rr = lane & 7;
    const uint32_t a_off = (uint32_t)((wid * 16 + (m & 1) * 8 + rr) * 80 + (m >> 1) * 16);
    const uint32_t b_lane = (uint32_t)(((lane >> 3) & 1) * 8 * 272 + (lane & 7) * 272 +
                                       (lane >> 4) * 16);

    for (int t = 0; t < 8; t++) {
        if (t < 7) {
            int nb = (t + 1) & 1;
            uint32_t dA = aA + (uint32_t)nb * 5120;
            uint32_t dB = aB + (uint32_t)nb * 8704;
            const char* As = Abase + (size_t)(t + 1) * 64;
            const char* Bs = Bbase + (size_t)(t + 1) * 32 * 512;
#pragma unroll
            for (int j = 0; j < 2; j++) {
                int u = tid + j * 128;
                int r = u >> 2, c = u & 3;
                cp16(dA + r * 80 + c * 16, As + (size_t)r * 512 + c * 16);
            }
#pragma unroll
            for (int j = 0; j < 4; j++) {
                int u = tid + j * 128;
                int r = u >> 4, c = u & 15;
                cp16(dB + r * 272 + c * 16, Bs + (size_t)r * 512 + c * 16);
            }
            CP_COMMIT();
            CP_WAIT(1);
        } else {
            CP_WAIT(0);
        }
        __syncthreads();

        const uint32_t bufA = aA + (uint32_t)(t & 1) * 5120;
        const uint32_t bufB = aB + (uint32_t)(t & 1) * 8704;

        uint32_t aq[2][4];
        ldsm_x4(aq[0], bufA + a_off);
        ldsm_x4(aq[1], bufA + a_off + 32);

#pragma unroll
        for (int ks = 0; ks < 2; ks++) {
#pragma unroll
            for (int j = 0; j < 8; j++) {
                uint32_t vb[4];
                ldsm_x4_t(vb, bufB + (uint32_t)(ks * 16 * 272 + j * 32) + b_lane);
                mma_bf16(acc[2 * j],     aq[ks], vb);
                mma_bf16(acc[2 * j + 1], aq[ks], vb + 2);
            }
        }
        __syncthreads();
    }

    const int gg = lane >> 2, tig = lane & 3;
    const int r0 = m0 + wid * 16 + gg;
#pragma unroll
    for (int j = 0; j < 16; j++) {
        int col = n0 + j * 8 + 2 * tig;
        float2 b2 = __ldg((const float2*)(bias + col));
        if (MODE == 1) {
            float* Cf = (float*)Cv;
            *(float2*)(Cf + (size_t)r0 * DD + col) =
                make_float2(acc[j][0] + b2.x, acc[j][1] + b2.y);
            *(float2*)(Cf + (size_t)(r0 + 8) * DD + col) =
                make_float2(acc[j][2] + b2.x, acc[j][3] + b2.y);
        } else {
            __half* Ch = (__half*)Cv;
            *(uint32_t*)(Ch + (size_t)r0 * DD + col) =
                pack_f16x2((acc[j][0] + b2.x) * scale, (acc[j][1] + b2.y) * scale);
            *(uint32_t*)(Ch + (size_t)(r0 + 8) * DD + col) =
                pack_f16x2((acc[j][2] + b2.x) * scale, (acc[j][3] + b2.y) * scale);
        }
    }
}

// ================= K2: QKV projections  ∥  edge scatter (one launch) ======
__global__ void __launch_bounds__(128) k2_kernel(const int* __restrict__ ei,
                                                 const float* __restrict__ bq,
                                                 const float* __restrict__ bk,
                                                 const float* __restrict__ bv) {
    int z = blockIdx.z;
    if (z < 3) {
        const float* bias = (z == 0) ? bq : (z == 1) ? bk : bv;
        __half* C = (z == 0) ? g_Qh : (z == 1) ? g_Kh : g_Vh;
        float scale = (z == 0) ? QSCALE : 1.f;
        gemm_core<0>(g_xb, g_Wb + (size_t)z * DD * DD, bias, C, scale);
    } else {
        int bid = blockIdx.x + blockIdx.y * 2;            // 0..127
        int e = (bid * 128 + threadIdx.x) * 4;            // 4 edges/thread
        uint4 s4 = *(const uint4*)(ei + e);
        uint4 d4 = *(const uint4*)(ei + EE + e);
        atomicOr(&g_adj[s4.x * NWORDS + (d4.x >> 5)], 1u << (d4.x & 31));
        atomicOr(&g_adj[d4.x * NWORDS + (s4.x >> 5)], 1u << (s4.x & 31));
        atomicOr(&g_adj[s4.y * NWORDS + (d4.y >> 5)], 1u << (d4.y & 31));
        atomicOr(&g_adj[d4.y * NWORDS + (s4.y >> 5)], 1u << (s4.y & 31));
        atomicOr(&g_adj[s4.z * NWORDS + (d4.z >> 5)], 1u << (d4.z & 31));
        atomicOr(&g_adj[d4.z * NWORDS + (s4.z >> 5)], 1u << (s4.z & 31));
        atomicOr(&g_adj[s4.w * NWORDS + (d4.w >> 5)], 1u << (d4.w & 31));
        atomicOr(&g_adj[d4.w * NWORDS + (s4.w >> 5)], 1u << (s4.w & 31));
    }
}

// ================= reach-2 mask (split neighbor list across 2 halves) =====
__global__ void __launch_bounds__(256) mask_kernel() {
    int n = blockIdx.x;
    int tid = threadIdx.x;
    int w = tid & 127;
    int h = tid >> 7;
    int lane = tid & 31;
    __shared__ uint16_t nbr[1024];
    __shared__ int cnt;
    __shared__ uint32_t accs[128];
    if (tid == 0) cnt = 0;
    __syncthreads();

    if (tid < 128) {
        uint32_t bits = g_adj[n * NWORDS + tid];
        int pc = __popc(bits);
        int pref = pc;
#pragma unroll
        for (int o = 1; o < 32; o <<= 1) {
            int v = __shfl_up_sync(0xFFFFFFFFu, pref, o);
            if (lane >= o) pref += v;
        }
        int wtot = __shfl_sync(0xFFFFFFFFu, pref, 31);
        int wbase = 0;
        if (lane == 0) wbase = atomicAdd(&cnt, wtot);
        wbase = __shfl_sync(0xFFFFFFFFu, wbase, 0);
        int off = wbase + pref - pc;
        while (bits) {
            int b = __ffs(bits) - 1;
            bits &= bits - 1;
            nbr[off++] = (uint16_t)((tid << 5) + b);
        }
    }
    __syncthreads();

    int c = cnt;
    uint32_t acc = 0;
    int i = h;
    for (; i + 6 < c; i += 8) {
        uint32_t a0 = g_adj[(int)nbr[i + 0] * NWORDS + w];
        uint32_t a1 = g_adj[(int)nbr[i + 2] * NWORDS + w];
        uint32_t a2 = g_adj[(int)nbr[i + 4] * NWORDS + w];
        uint32_t a3 = g_adj[(int)nbr[i + 6] * NWORDS + w];
        acc |= (a0 | a1) | (a2 | a3);
    }
    for (; i < c; i += 2)
        acc |= g_adj[(int)nbr[i] * NWORDS + w];

    if (h == 0) accs[w] = acc;
    __syncthreads();
    if (h == 1) g_mask[n * NWORDS + w] = accs[w] | acc;
}

__global__ void __launch_bounds__(128) wo_gemm_kernel(const float* __restrict__ bo) {
    gemm_core<1>(g_attb, g_Wb + (size_t)3 * DD * DD, bo, g_tmp, 1.f);
}

// ================= attention: split-KV + column-split warps ===============
// grid (32, 8, 2). CTA: 256 threads / 8 warps, 128 queries, 16 kv tiles.
// Warp = 32 q rows x 64 kv cols: warps 0-3 cols 0-63, warps 4-7 cols 64-127.
// K/V fragments amortized over 2 row groups; O/l column partials combined
// once at the end via smem staging.
struct AttnSmemH {
    __half Qs[128 * 32];       // 8192 B (64B rows)
    __half Ks[2][128 * 40];    // 2 x 10240 B
    __half Vs[2][128 * 40];    // 2 x 10240 B
};                             // total 49152 B

__global__ void __launch_bounds__(256, 2) attn_kernel() {
    __shared__ AttnSmemH sm;
    const int tid = threadIdx.x;
    const int wid = tid >> 5;
    const int lane = tid & 31;
    const int h = blockIdx.y;
    const int q0 = blockIdx.x * 128;
    const int z = blockIdx.z;
    const int t0 = z * TILES_PER_SPLIT;
    const int t1 = t0 + TILES_PER_SPLIT;

    const int rgrp = wid & 3;          // row group: 32 q rows
    const int cgrp = wid >> 2;         // kv column half: 0 or 1
    const int wq0 = rgrp * 32;

    const uint32_t s_q = smem_u32(sm.Qs);
    const uint32_t s_k0 = smem_u32(sm.Ks[0]);
    const uint32_t s_v0 = smem_u32(sm.Vs[0]);

    const char* ksrc = (const char*)(g_Kh + h * HD);
    const char* vsrc = (const char*)(g_Vh + h * HD);

    // ---- prologue: Q + K(t0)/V(t0) via cp.async ----
    {
        const char* qsrc = (const char*)(g_Qh + (size_t)q0 * DD + h * HD);
        size_t tb = (size_t)t0 * 128 * 512;
#pragma unroll
        for (int j = 0; j < 2; j++) {
            int chunk = tid + j * 256;
            int r = chunk >> 2, c = chunk & 3;
            cp16(s_q + (uint32_t)(r * 64 + c * 16), qsrc + (size_t)r * 512 + c * 16);
        }
#pragma unroll
        for (int j = 0; j < 2; j++) {
            int chunk = tid + j * 256;
            int r = chunk >> 2, c = chunk & 3;
            uint32_t off = (uint32_t)(r * 80 + c * 16);
            size_t gs = tb + (size_t)r * 512 + c * 16;
            cp16(s_k0 + off, ksrc + gs);
            cp16(s_v0 + off, vsrc + gs);
        }
        CP_COMMIT();
    }

    const int g = lane >> 2, tig = lane & 3;
    const int row0 = q0 + wq0 + g;

    // mask words for 4 row octets (uint2 = this warp's 64 kv cols)
    uint2 mw[4];
#pragma unroll
    for (int i = 0; i < 4; i++)
        mw[i] = *(const uint2*)(g_mask + (size_t)(row0 + i * 8) * NWORDS + t0 * 4 + cgrp * 2);

    CP_WAIT(0);
    __syncthreads();

    // ---- Q fragments for 32 rows (two 16-row groups) ----
    uint32_t aqlo[2][4], aqhi[2][4];
    {
        int m = lane >> 3, rr = lane & 7;
        uint32_t base = s_q + (uint32_t)((wq0 + (m & 1) * 8 + rr) * 64 + (m >> 1) * 16);
        ldsm_x4(aqlo[0], base);
        ldsm_x4(aqlo[1], base + 32);
        ldsm_x4(aqhi[0], base + 16 * 64);
        ldsm_x4(aqhi[1], base + 16 * 64 + 32);
    }

    // persistent f16x2 O accumulators (two row groups x 32 d cols)
    uint32_t of[4][2], o2[4][2];
#pragma unroll
    for (int v = 0; v < 4; v++) { of[v][0] = of[v][1] = 0u; o2[v][0] = o2[v][1] = 0u; }
    float ls[4] = {0.f, 0.f, 0.f, 0.f};

    const uint32_t k_lane_off = (uint32_t)((lane & 7) * 80 + (lane >> 3) * 16);
    const uint32_t v_lane_off = (uint32_t)(((lane >> 3) & 1) * 8 * 80 + (lane & 7) * 80 +
                                           (lane >> 4) * 16);

    for (int t = t0; t < t1; t++) {
        int buf = t & 1;
        uint2 mw_n[4];
        if (t < t1 - 1) {
#pragma unroll
            for (int i = 0; i < 4; i++)
                mw_n[i] = *(const uint2*)(g_mask + (size_t)(row0 + i * 8) * NWORDS +
                                          (t + 1) * 4 + cgrp * 2);
            int nb = (t + 1) & 1;
            uint32_t skb = s_k0 + (uint32_t)nb * 10240;
            uint32_t svb = s_v0 + (uint32_t)nb * 10240;
            size_t tb = (size_t)(t + 1) * 128 * 512;
#pragma unroll
            for (int j = 0; j < 2; j++) {
                int chunk = tid + j * 256;
                int r = chunk >> 2, c = chunk & 3;
                uint32_t off = (uint32_t)(r * 80 + c * 16);
                size_t gs = tb + (size_t)r * 512 + c * 16;
                cp16(skb + off, ksrc + gs);
                cp16(svb + off, vsrc + gs);
            }
            CP_COMMIT();
            CP_WAIT(1);
        } else {
            CP_WAIT(0);
        }
        __syncthreads();

        const uint32_t kb_base = s_k0 + (uint32_t)buf * 10240;
        const uint32_t vb_base = s_v0 + (uint32_t)buf * 10240;

        uint32_t acc[4] = {0u, 0u, 0u, 0u};   // per-tile f16x2 row-sum accums
#pragma unroll
        for (int qd = 0; qd < 2; qd++) {
            // K fragments for this quad (4 n-tiles of 8 kv rows)
            uint32_t kb[4][4];
#pragma unroll
            for (int nt = 0; nt < 4; nt++)
                ldsm_x4(kb[nt], kb_base +
                        (uint32_t)((cgrp * 8 + qd * 4 + nt) * (8 * 80)) + k_lane_off);
            // mask prep for 4 row octets
            uint32_t y1[4], y2[4];
#pragma unroll
            for (int i = 0; i < 4; i++) {
                uint32_t w = (qd ? mw[i].y : mw[i].x) >> (2 * tig);
                y1[i] = (w & 0x01010101u) << 7;
                y2[i] = (w & 0x02020202u) << 6;
            }
            uint32_t apA[2][4], apB[2][4];
#pragma unroll
            for (int nt = 0; nt < 4; nt++) {
                uint32_t sdA[2] = {0u, 0u}, sdB[2] = {0u, 0u};
                mma_h(sdA, aqlo[0], kb[nt]);
                mma_h(sdA, aqlo[1], kb[nt] + 2);
                mma_h(sdB, aqhi[0], kb[nt]);
                mma_h(sdB, aqhi[1], kb[nt] + 2);
                uint32_t sel = 0xCC88u + (uint32_t)nt * 0x1111u;
                uint32_t p0 = ex2_f16x2(sdA[0]) & prmt(y1[0], y2[0], sel);
                uint32_t p1 = ex2_f16x2(sdA[1]) & prmt(y1[1], y2[1], sel);
                uint32_t p2 = ex2_f16x2(sdB[0]) & prmt(y1[2], y2[2], sel);
                uint32_t p3 = ex2_f16x2(sdB[1]) & prmt(y1[3], y2[3], sel);
                acc[0] = hadd2(acc[0], p0);
                acc[1] = hadd2(acc[1], p1);
                acc[2] = hadd2(acc[2], p2);
                acc[3] = hadd2(acc[3], p3);
                apA[nt >> 1][(nt & 1) * 2 + 0] = p0;
                apA[nt >> 1][(nt & 1) * 2 + 1] = p1;
                apB[nt >> 1][(nt & 1) * 2 + 0] = p2;
                apB[nt >> 1][(nt & 1) * 2 + 1] = p3;
            }
            // PV for this quad's 32 kv cols; V fragments shared by both groups
#pragma unroll
            for (int j = 0; j < 2; j++) {
                int ktg = cgrp * 4 + qd * 2 + j;
                uint32_t vb[4];
                uint32_t base = vb_base + (uint32_t)ktg * (16 * 80) + v_lane_off;
                ldsm_x4_t(vb, base);
                mma_h(of[0], apA[j], vb);
                mma_h(of[1], apA[j], vb + 2);
                mma_h(o2[0], apB[j], vb);
                mma_h(o2[1], apB[j], vb + 2);
                ldsm_x4_t(vb, base + 32);
                mma_h(of[2], apA[j], vb);
                mma_h(of[3], apA[j], vb + 2);
                mma_h(o2[2], apB[j], vb);
                mma_h(o2[3], apB[j], vb + 2);
            }
        }
        // flush per-tile row sums to fp32
#pragma unroll
        for (int i = 0; i < 4; i++) {
            float2 f = h2_to_f2(acc[i]);
            ls[i] += f.x + f.y;
        }

        if (t < t1 - 1) {
#pragma unroll
            for (int i = 0; i < 4; i++) mw[i] = mw_n[i];
        }
        __syncthreads();
    }

    // quad-reduce row sums (cols spread over tig lanes)
#pragma unroll
    for (int i = 0; i < 4; i++) {
        ls[i] += __shfl_xor_sync(0xFFFFFFFFu, ls[i], 1);
        ls[i] += __shfl_xor_sync(0xFFFFFFFFu, ls[i], 2);
    }

    // ---- combine column halves: warps 4-7 stage, warps 0-3 reduce+write ----
    uint32_t* stage = (uint32_t*)&sm;   // Q/K/V buffers dead; 10240 B used
    __syncthreads();
    if (cgrp == 1) {
        uint32_t* p = stage + ((size_t)rgrp * 32 + lane) * 20;
#pragma unroll
        for (int v = 0; v < 4; v++) {
            p[v * 2] = of[v][0];  p[v * 2 + 1] = of[v][1];
            p[8 + v * 2] = o2[v][0]; p[8 + v * 2 + 1] = o2[v][1];
        }
#pragma unroll
        for (int i = 0; i < 4; i++) p[16 + i] = __float_as_uint(ls[i]);
    }
    __syncthreads();
    if (cgrp == 0) {
        const uint32_t* p = stage + ((size_t)rgrp * 32 + lane) * 20;
        float* d0 = g_pO + (size_t)z * NN * DD + (size_t)row0 * DD + h * HD + 2 * tig;
#pragma unroll
        for (int grp = 0; grp < 2; grp++) {
            const uint32_t (*oo)[2] = grp ? o2 : of;
            const uint32_t* pp = p + grp * 8;
            float* dA = d0 + (size_t)(grp * 16) * DD;
            float* dB = dA + 8 * DD;
#pragma unroll
            for (int v = 0; v < 4; v++) {
                float2 a0 = h2_to_f2(oo[v][0]), b0 = h2_to_f2(pp[v * 2]);
                float2 a1 = h2_to_f2(oo[v][1]), b1 = h2_to_f2(pp[v * 2 + 1]);
                *(float2*)(dA + v * 8) = make_float2(a0.x + b0.x, a0.y + b0.y);
                *(float2*)(dB + v * 8) = make_float2(a1.x + b1.x, a1.y + b1.y);
            }
        }
        if (tig == 0) {
#pragma unroll
            for (int i = 0; i < 4; i++)
                g_pl[z * HH * NN + h * NN + row0 + i * 8] =
                    ls[i] + __uint_as_float(p[16 + i]);
        }
    }
}

// ================= combine split-KV partials -> bf16 attended =============
__global__ void __launch_bounds__(256) combine_kernel() {
    int i = (blockIdx.x * 256 + threadIdx.x) * 4;   // over NN*DD
    int n = i >> 8;            // DD = 256
    int c = i & 255;
    int h = c >> 5;
    float l = g_pl[h * NN + n] + g_pl[HH * NN + h * NN + n];
    float inv = 1.f / l;
    float4 a = *(const float4*)(g_pO + i);
    float4 b = *(const float4*)(g_pO + NN * DD + i);
    *(uint2*)(g_attb + i) = make_uint2(
        pack_bf16x2((a.x + b.x) * inv, (a.y + b.y) * inv),
        pack_bf16x2((a.z + b.z) * inv, (a.w + b.w) * inv));
}

// ================= residual + LayerNorm (warp-shuffle) =================
__global__ void ln_kernel(const float* __restrict__ tmp,
                          const float* __restrict__ x,
                          const float* __restrict__ w,
                          const float* __restrict__ b,
                          float* __restrict__ out) {
    int n = blockIdx.x;
    int tid = threadIdx.x;  // 256 == DD
    int wid = tid >> 5, lane = tid & 31;
    float v = tmp[n * DD + tid] + x[n * DD + tid];
    float s1 = v, s2 = v * v;
#pragma unroll
    for (int o = 16; o > 0; o >>= 1) {
        s1 += __shfl_xor_sync(0xFFFFFFFFu, s1, o);
        s2 += __shfl_xor_sync(0xFFFFFFFFu, s2, o);
    }
    __shared__ float a1[8], a2[8];
    if (lane == 0) { a1[wid] = s1; a2[wid] = s2; }
    __syncthreads();
    float t1 = 0.f, t2 = 0.f;
#pragma unroll
    for (int i = 0; i < 8; i++) { t1 += a1[i]; t2 += a2[i]; }
    float mu = t1 * (1.f / 256.f);
    float var = t2 * (1.f / 256.f) - mu * mu;
    float inv = rsqrtf(var + 1e-5f);
    out[n * DD + tid] = (v - mu) * inv * w[tid] + b[tid];
}

// ================= launch =================
extern "C" void kernel_launch(void* const* d_in, const int* in_sizes, int n_in,
                              void* d_out, int out_size) {
    const float* x   = (const float*)d_in[0];
    const int*   ei  = (const int*)d_in[1];
    const float* Wq  = (const float*)d_in[2];
    const float* bq  = (const float*)d_in[3];
    const float* Wk  = (const float*)d_in[4];
    const float* bk  = (const float*)d_in[5];
    const float* Wv  = (const float*)d_in[6];
    const float* bv  = (const float*)d_in[7];
    const float* Wo  = (const float*)d_in[8];
    const float* bo  = (const float*)d_in[9];
    const float* lnw = (const float*)d_in[10];
    const float* lnb = (const float*)d_in[11];
    float* out = (float*)d_out;

    float* gT;
    cudaGetSymbolAddress((void**)&gT, g_tmp);

    // K1: casts ∥ adjacency init
    k1_kernel<<<3328, 256>>>(x, Wq, Wk, Wv, Wo);
    // K2: QKV projections ∥ edge scatter
    k2_kernel<<<dim3(DD / 128, NN / 64, 4), 128>>>(ei, bq, bk, bv);
    // reach-2 mask
    mask_kernel<<<NN, 256>>>();
    // tensor-core attention, split-KV x column-split warps
    attn_kernel<<<dim3(NN / 128, HH, NSPLIT), 256>>>();
    // combine partials
    combine_kernel<<<NN * DD / 1024, 256>>>();
    // output projection (tensor core, fp32 out) + residual + LN
    wo_gemm_kernel<<<dim3(DD / 128, NN / 64), 128>>>(bo);
    ln_kernel<<<NN, 256>>>(gT, x, lnw, lnb, out);
}

// round 13
// speedup vs baseline: 1.0191x; 1.0191x over previous
#include <cuda_runtime.h>
#include <cuda_bf16.h>
#include <cuda_fp16.h>
#include <math.h>
#include <stdint.h>

// ---------------- problem constants ----------------
#define NN 4096
#define DD 256
#define HH 8
#define HD 32
#define EE 65536
#define NWORDS 128
// (1/sqrt(32)) * log2(e): folded into Q so softmax weight = exp2(S)
#define QSCALE 0.25503486f
#define NSPLIT 2
#define TILES_PER_SPLIT 16

// ---------------- scratch globals (no allocs allowed) ----------------
__device__ uint32_t g_adj[NN * NWORDS];
__device__ uint32_t g_mask[NN * NWORDS];
__device__ __nv_bfloat16 g_xb[NN * DD];
__device__ __nv_bfloat16 g_Wb[4 * DD * DD];   // Wq, Wk, Wv, Wo (bf16)
__device__ __half g_Qh[NN * DD];              // fp16, pre-scaled by QSCALE
__device__ __half g_Kh[NN * DD];
__device__ __half g_Vh[NN * DD];
__device__ __nv_bfloat16 g_attb[NN * DD];     // attention output (bf16)
__device__ float g_tmp[NN * DD];
__device__ float g_pO[NSPLIT * NN * DD];      // split-KV partial O (unnormalized)
__device__ float g_pl[NSPLIT * HH * NN];      // split-KV partial row sums

// ---------------- PTX helpers ----------------
__device__ __forceinline__ uint32_t smem_u32(const void* p) {
    uint32_t a;
    asm("{ .reg .u64 t; cvta.to.shared.u64 t, %1; cvt.u32.u64 %0, t; }"
        : "=r"(a) : "l"(p));
    return a;
}
__device__ __forceinline__ uint32_t pack_bf16x2(float lo, float hi) {
    uint32_t r;
    asm("cvt.rn.bf16x2.f32 %0, %1, %2;" : "=r"(r) : "f"(hi), "f"(lo));
    return r;
}
__device__ __forceinline__ uint32_t pack_f16x2(float lo, float hi) {
    uint32_t r;
    asm("cvt.rn.f16x2.f32 %0, %1, %2;" : "=r"(r) : "f"(hi), "f"(lo));
    return r;
}
__device__ __forceinline__ uint32_t ex2_f16x2(uint32_t x) {
    uint32_t y;
    asm("ex2.approx.f16x2 %0, %1;" : "=r"(y) : "r"(x));
    return y;
}
__device__ __forceinline__ uint32_t hadd2(uint32_t a, uint32_t b) {
    uint32_t d;
    asm("add.rn.f16x2 %0, %1, %2;" : "=r"(d) : "r"(a), "r"(b));
    return d;
}
__device__ __forceinline__ uint32_t prmt(uint32_t a, uint32_t b, uint32_t sel) {
    uint32_t d;
    asm("prmt.b32 %0, %1, %2, %3;" : "=r"(d) : "r"(a), "r"(b), "r"(sel));
    return d;
}
__device__ __forceinline__ float2 h2_to_f2(uint32_t u) {
    __half2 h = *reinterpret_cast<__half2*>(&u);
    return __half22float2(h);
}
__device__ __forceinline__ void ldsm_x4(uint32_t* r, uint32_t addr) {
    asm volatile("ldmatrix.sync.aligned.m8n8.x4.shared.b16 {%0,%1,%2,%3}, [%4];"
        : "=r"(r[0]), "=r"(r[1]), "=r"(r[2]), "=r"(r[3]) : "r"(addr));
}
__device__ __forceinline__ void ldsm_x4_t(uint32_t* r, uint32_t addr) {
    asm volatile("ldmatrix.sync.aligned.m8n8.x4.trans.shared.b16 {%0,%1,%2,%3}, [%4];"
        : "=r"(r[0]), "=r"(r[1]), "=r"(r[2]), "=r"(r[3]) : "r"(addr));
}
__device__ __forceinline__ void mma_bf16(float* c, const uint32_t* a, const uint32_t* b) {
    asm volatile(
        "mma.sync.aligned.m16n8k16.row.col.f32.bf16.bf16.f32 "
        "{%0,%1,%2,%3}, {%4,%5,%6,%7}, {%8,%9}, {%0,%1,%2,%3};"
        : "+f"(c[0]), "+f"(c[1]), "+f"(c[2]), "+f"(c[3])
        : "r"(a[0]), "r"(a[1]), "r"(a[2]), "r"(a[3]), "r"(b[0]), "r"(b[1]));
}
// fp16 in, fp16 accumulate
__device__ __forceinline__ void mma_h(uint32_t* d, const uint32_t* a, const uint32_t* b) {
    asm volatile(
        "mma.sync.aligned.m16n8k16.row.col.f16.f16.f16.f16 "
        "{%0,%1}, {%2,%3,%4,%5}, {%6,%7}, {%0,%1};"
        : "+r"(d[0]), "+r"(d[1])
        : "r"(a[0]), "r"(a[1]), "r"(a[2]), "r"(a[3]), "r"(b[0]), "r"(b[1]));
}
__device__ __forceinline__ void cp16(uint32_t dst, const void* src) {
    asm volatile("cp.async.cg.shared.global [%0], [%1], 16;" :: "r"(dst), "l"(src));
}
#define CP_COMMIT() asm volatile("cp.async.commit_group;" ::: "memory")
#define CP_WAIT(n)  asm volatile("cp.async.wait_group %0;" :: "n"(n) : "memory")

// ================= K1: bf16 casts  ∥  adjacency init (one launch) =========
__global__ void __launch_bounds__(256) k1_kernel(const float* __restrict__ x,
                                                 const float* __restrict__ Wq,
                                                 const float* __restrict__ Wk,
                                                 const float* __restrict__ Wv,
                                                 const float* __restrict__ Wo) {
    int b = blockIdx.x;
    if (b < 1280) {
        int i = (b * 256 + threadIdx.x) * 4;
        const float* src;
        __nv_bfloat16* dst;
        if (i < NN * DD) {
            src = x + i; dst = g_xb + i;
        } else {
            int j = i - NN * DD;
            int w = j >> 16;
            int o = j & 65535;
            src = ((w == 0) ? Wq : (w == 1) ? Wk : (w == 2) ? Wv : Wo) + o;
            dst = g_Wb + w * (DD * DD) + o;
        }
        float4 v = *(const float4*)src;
        *(uint2*)dst = make_uint2(pack_bf16x2(v.x, v.y), pack_bf16x2(v.z, v.w));
    } else {
        int idx = (b - 1280) * 256 + threadIdx.x;
        int n = idx >> 7, w = idx & 127;
        uint32_t v = 0;
        if (w == (n >> 5)) v = 1u << (n & 31);
        g_adj[idx] = v;
    }
}

// ================= bf16 tensor-core GEMM core =================
template <int MODE>
__device__ __forceinline__ void gemm_core(const __nv_bfloat16* __restrict__ A,
                                          const __nv_bfloat16* __restrict__ W,
                                          const float* __restrict__ bias,
                                          void* __restrict__ Cv, float scale) {
    __shared__ __nv_bfloat16 sA[2][64 * 40];
    __shared__ __nv_bfloat16 sB[2][32 * 136];

    const int tid = threadIdx.x;
    const int wid = tid >> 5;
    const int lane = tid & 31;
    const int m0 = blockIdx.y * 64;
    const int n0 = blockIdx.x * 128;

    const uint32_t aA = smem_u32(sA);
    const uint32_t aB = smem_u32(sB);
    const char* Abase = (const char*)A + (size_t)m0 * (DD * 2);
    const char* Bbase = (const char*)W + (size_t)n0 * 2;

    {
#pragma unroll
        for (int j = 0; j < 2; j++) {
            int t = tid + j * 128;
            int r = t >> 2, c = t & 3;
            cp16(aA + r * 80 + c * 16, Abase + (size_t)r * 512 + c * 16);
        }
#pragma unroll
        for (int j = 0; j < 4; j++) {
            int t = tid + j * 128;
            int r = t >> 4, c = t & 15;
            cp16(aB + r * 272 + c * 16, Bbase + (size_t)r * 512 + c * 16);
        }
        CP_COMMIT();
    }

    float acc[16][4];
#pragma unroll
    for (int j = 0; j < 16; j++)
        acc[j][0] = acc[j][1] = acc[j][2] = acc[j][3] = 0.f;

    const int m = lane >> 3, rr = lane & 7;
    const uint32_t a_off = (uint32_t)((wid * 16 + (m & 1) * 8 + rr) * 80 + (m >> 1) * 16);
    const uint32_t b_lane = (uint32_t)(((lane >> 3) & 1) * 8 * 272 + (lane & 7) * 272 +
                                       (lane >> 4) * 16);

    for (int t = 0; t < 8; t++) {
        if (t < 7) {
            int nb = (t + 1) & 1;
            uint32_t dA = aA + (uint32_t)nb * 5120;
            uint32_t dB = aB + (uint32_t)nb * 8704;
            const char* As = Abase + (size_t)(t + 1) * 64;
            const char* Bs = Bbase + (size_t)(t + 1) * 32 * 512;
#pragma unroll
            for (int j = 0; j < 2; j++) {
                int u = tid + j * 128;
                int r = u >> 2, c = u & 3;
                cp16(dA + r * 80 + c * 16, As + (size_t)r * 512 + c * 16);
            }
#pragma unroll
            for (int j = 0; j < 4; j++) {
                int u = tid + j * 128;
                int r = u >> 4, c = u & 15;
                cp16(dB + r * 272 + c * 16, Bs + (size_t)r * 512 + c * 16);
            }
            CP_COMMIT();
            CP_WAIT(1);
        } else {
            CP_WAIT(0);
        }
        __syncthreads();

        const uint32_t bufA = aA + (uint32_t)(t & 1) * 5120;
        const uint32_t bufB = aB + (uint32_t)(t & 1) * 8704;

        uint32_t aq[2][4];
        ldsm_x4(aq[0], bufA + a_off);
        ldsm_x4(aq[1], bufA + a_off + 32);

#pragma unroll
        for (int ks = 0; ks < 2; ks++) {
#pragma unroll
            for (int j = 0; j < 8; j++) {
                uint32_t vb[4];
                ldsm_x4_t(vb, bufB + (uint32_t)(ks * 16 * 272 + j * 32) + b_lane);
                mma_bf16(acc[2 * j],     aq[ks], vb);
                mma_bf16(acc[2 * j + 1], aq[ks], vb + 2);
            }
        }
        __syncthreads();
    }

    const int gg = lane >> 2, tig = lane & 3;
    const int r0 = m0 + wid * 16 + gg;
#pragma unroll
    for (int j = 0; j < 16; j++) {
        int col = n0 + j * 8 + 2 * tig;
        float2 b2 = __ldg((const float2*)(bias + col));
        if (MODE == 1) {
            float* Cf = (float*)Cv;
            *(float2*)(Cf + (size_t)r0 * DD + col) =
                make_float2(acc[j][0] + b2.x, acc[j][1] + b2.y);
            *(float2*)(Cf + (size_t)(r0 + 8) * DD + col) =
                make_float2(acc[j][2] + b2.x, acc[j][3] + b2.y);
        } else {
            __half* Ch = (__half*)Cv;
            *(uint32_t*)(Ch + (size_t)r0 * DD + col) =
                pack_f16x2((acc[j][0] + b2.x) * scale, (acc[j][1] + b2.y) * scale);
            *(uint32_t*)(Ch + (size_t)(r0 + 8) * DD + col) =
                pack_f16x2((acc[j][2] + b2.x) * scale, (acc[j][3] + b2.y) * scale);
        }
    }
}

// ================= K2: QKV projections  ∥  edge scatter (one launch) ======
__global__ void __launch_bounds__(128) k2_kernel(const int* __restrict__ ei,
                                                 const float* __restrict__ bq,
                                                 const float* __restrict__ bk,
                                                 const float* __restrict__ bv) {
    int z = blockIdx.z;
    if (z < 3) {
        const float* bias = (z == 0) ? bq : (z == 1) ? bk : bv;
        __half* C = (z == 0) ? g_Qh : (z == 1) ? g_Kh : g_Vh;
        float scale = (z == 0) ? QSCALE : 1.f;
        gemm_core<0>(g_xb, g_Wb + (size_t)z * DD * DD, bias, C, scale);
    } else {
        int bid = blockIdx.x + blockIdx.y * 2;            // 0..127
        int e = (bid * 128 + threadIdx.x) * 4;            // 4 edges/thread
        uint4 s4 = *(const uint4*)(ei + e);
        uint4 d4 = *(const uint4*)(ei + EE + e);
        atomicOr(&g_adj[s4.x * NWORDS + (d4.x >> 5)], 1u << (d4.x & 31));
        atomicOr(&g_adj[d4.x * NWORDS + (s4.x >> 5)], 1u << (s4.x & 31));
        atomicOr(&g_adj[s4.y * NWORDS + (d4.y >> 5)], 1u << (d4.y & 31));
        atomicOr(&g_adj[d4.y * NWORDS + (s4.y >> 5)], 1u << (s4.y & 31));
        atomicOr(&g_adj[s4.z * NWORDS + (d4.z >> 5)], 1u << (d4.z & 31));
        atomicOr(&g_adj[d4.z * NWORDS + (s4.z >> 5)], 1u << (s4.z & 31));
        atomicOr(&g_adj[s4.w * NWORDS + (d4.w >> 5)], 1u << (d4.w & 31));
        atomicOr(&g_adj[d4.w * NWORDS + (s4.w >> 5)], 1u << (s4.w & 31));
    }
}

// ================= reach-2 mask (split neighbor list across 2 halves) =====
__global__ void __launch_bounds__(256) mask_kernel() {
    int n = blockIdx.x;
    int tid = threadIdx.x;
    int w = tid & 127;
    int h = tid >> 7;
    int lane = tid & 31;
    __shared__ uint16_t nbr[1024];
    __shared__ int cnt;
    __shared__ uint32_t accs[128];
    if (tid == 0) cnt = 0;
    __syncthreads();

    if (tid < 128) {
        uint32_t bits = g_adj[n * NWORDS + tid];
        int pc = __popc(bits);
        int pref = pc;
#pragma unroll
        for (int o = 1; o < 32; o <<= 1) {
            int v = __shfl_up_sync(0xFFFFFFFFu, pref, o);
            if (lane >= o) pref += v;
        }
        int wtot = __shfl_sync(0xFFFFFFFFu, pref, 31);
        int wbase = 0;
        if (lane == 0) wbase = atomicAdd(&cnt, wtot);
        wbase = __shfl_sync(0xFFFFFFFFu, wbase, 0);
        int off = wbase + pref - pc;
        while (bits) {
            int b = __ffs(bits) - 1;
            bits &= bits - 1;
            nbr[off++] = (uint16_t)((tid << 5) + b);
        }
    }
    __syncthreads();

    int c = cnt;
    uint32_t acc = 0;
    int i = h;
    for (; i + 6 < c; i += 8) {
        uint32_t a0 = g_adj[(int)nbr[i + 0] * NWORDS + w];
        uint32_t a1 = g_adj[(int)nbr[i + 2] * NWORDS + w];
        uint32_t a2 = g_adj[(int)nbr[i + 4] * NWORDS + w];
        uint32_t a3 = g_adj[(int)nbr[i + 6] * NWORDS + w];
        acc |= (a0 | a1) | (a2 | a3);
    }
    for (; i < c; i += 2)
        acc |= g_adj[(int)nbr[i] * NWORDS + w];

    if (h == 0) accs[w] = acc;
    __syncthreads();
    if (h == 1) g_mask[n * NWORDS + w] = accs[w] | acc;
}

__global__ void __launch_bounds__(128) wo_gemm_kernel(const float* __restrict__ bo) {
    gemm_core<1>(g_attb, g_Wb + (size_t)3 * DD * DD, bo, g_tmp, 1.f);
}

// ================= attention: split-KV, 4 CTAs/SM =========================
// grid (32, 8, 2). CTA: 256 threads / 8 warps, 128 queries, 16 kv tiles.
// Masks loaded per-tile via LDG (L2-resident) before the barrier — no
// register double-buffer, freeing regs for 4-CTA occupancy.
struct AttnSmemH {
    __half Qs[128 * 32];       // 8192 B (64B rows)
    __half Ks[2][128 * 40];    // 2 x 10240 B
    __half Vs[2][128 * 40];    // 2 x 10240 B
};                             // total 49152 B

__global__ void __launch_bounds__(256, 4) attn_kernel() {
    __shared__ AttnSmemH sm;
    const int tid = threadIdx.x;
    const int wid = tid >> 5;
    const int lane = tid & 31;
    const int h = blockIdx.y;
    const int q0 = blockIdx.x * 128;
    const int z = blockIdx.z;
    const int t0 = z * TILES_PER_SPLIT;
    const int t1 = t0 + TILES_PER_SPLIT;

    const uint32_t s_q = smem_u32(sm.Qs);
    const uint32_t s_k0 = smem_u32(sm.Ks[0]);
    const uint32_t s_v0 = smem_u32(sm.Vs[0]);

    const char* ksrc = (const char*)(g_Kh + h * HD);
    const char* vsrc = (const char*)(g_Vh + h * HD);

    // ---- prologue: Q + K(t0)/V(t0) via cp.async ----
    {
        const char* qsrc = (const char*)(g_Qh + (size_t)q0 * DD + h * HD);
        size_t tb = (size_t)t0 * 128 * 512;
#pragma unroll
        for (int j = 0; j < 2; j++) {
            int chunk = tid + j * 256;
            int r = chunk >> 2, c = chunk & 3;
            cp16(s_q + (uint32_t)(r * 64 + c * 16), qsrc + (size_t)r * 512 + c * 16);
        }
#pragma unroll
        for (int j = 0; j < 2; j++) {
            int chunk = tid + j * 256;
            int r = chunk >> 2, c = chunk & 3;
            uint32_t off = (uint32_t)(r * 80 + c * 16);
            size_t gs = tb + (size_t)r * 512 + c * 16;
            cp16(s_k0 + off, ksrc + gs);
            cp16(s_v0 + off, vsrc + gs);
        }
        CP_COMMIT();
    }

    const int wq0 = wid * 16;
    const int g = lane >> 2, tig = lane & 3;
    const int row0 = q0 + wq0 + g;
    const uint32_t* mrow_lo = g_mask + (size_t)row0 * NWORDS;
    const uint32_t* mrow_hi = g_mask + (size_t)(row0 + 8) * NWORDS;

    CP_WAIT(0);
    __syncthreads();

    uint32_t aq[2][4];
    {
        int m = lane >> 3, rr = lane & 7;
        uint32_t base = s_q + (uint32_t)((wq0 + (m & 1) * 8 + rr) * 64 + (m >> 1) * 16);
        ldsm_x4(aq[0], base);
        ldsm_x4(aq[1], base + 32);
    }

    // persistent f16x2 O accumulators (flushed once at the end)
    uint32_t of[4][2];
#pragma unroll
    for (int v = 0; v < 4; v++) { of[v][0] = 0u; of[v][1] = 0u; }
    float ls0 = 0.f, ls1 = 0.f;

    const uint32_t k_lane_off = (uint32_t)((lane & 7) * 80 + (lane >> 3) * 16);
    const uint32_t v_lane_off = (uint32_t)(((lane >> 3) & 1) * 8 * 80 + (lane & 7) * 80 +
                                           (lane >> 4) * 16);

    for (int t = t0; t < t1; t++) {
        int buf = t & 1;
        if (t < t1 - 1) {
            int nb = (t + 1) & 1;
            uint32_t skb = s_k0 + (uint32_t)nb * 10240;
            uint32_t svb = s_v0 + (uint32_t)nb * 10240;
            size_t tb = (size_t)(t + 1) * 128 * 512;
#pragma unroll
            for (int j = 0; j < 2; j++) {
                int chunk = tid + j * 256;
                int r = chunk >> 2, c = chunk & 3;
                uint32_t off = (uint32_t)(r * 80 + c * 16);
                size_t gs = tb + (size_t)r * 512 + c * 16;
                cp16(skb + off, ksrc + gs);
                cp16(svb + off, vsrc + gs);
            }
            CP_COMMIT();
            CP_WAIT(1);
        } else {
            CP_WAIT(0);
        }
        // issue this tile's mask loads before the barrier (L2-resident)
        uint4 mw_lo = __ldg((const uint4*)(mrow_lo + t * 4));
        uint4 mw_hi = __ldg((const uint4*)(mrow_hi + t * 4));
        __syncthreads();

        const uint32_t kb_base = s_k0 + (uint32_t)buf * 10240;
        const uint32_t vb_base = s_v0 + (uint32_t)buf * 10240;
        const uint32_t mwl[4] = {mw_lo.x, mw_lo.y, mw_lo.z, mw_lo.w};
        const uint32_t mwh[4] = {mw_hi.x, mw_hi.y, mw_hi.z, mw_hi.w};

        uint32_t acc01 = 0, acc23 = 0;   // per-tile f16x2 row-sum accumulators
#pragma unroll
        for (int qd = 0; qd < 4; qd++) {
            uint32_t kb[4][4];
#pragma unroll
            for (int nt = 0; nt < 4; nt++)
                ldsm_x4(kb[nt], kb_base + (uint32_t)((qd * 4 + nt) * (8 * 80)) + k_lane_off);
            uint32_t w0 = mwl[qd] >> (2 * tig);
            uint32_t w1 = mwh[qd] >> (2 * tig);
            uint32_t y1 = (w0 & 0x01010101u) << 7;
            uint32_t y2 = (w0 & 0x02020202u) << 6;
            uint32_t z1 = (w1 & 0x01010101u) << 7;
            uint32_t z2 = (w1 & 0x02020202u) << 6;
            uint32_t ap[2][4];
#pragma unroll
            for (int nt = 0; nt < 4; nt++) {
                uint32_t sd[2] = {0u, 0u};
                mma_h(sd, aq[0], kb[nt]);
                mma_h(sd, aq[1], kb[nt] + 2);
                uint32_t sel = 0xCC88u + (uint32_t)nt * 0x1111u;
                uint32_t p01 = ex2_f16x2(sd[0]) & prmt(y1, y2, sel);
                uint32_t p23 = ex2_f16x2(sd[1]) & prmt(z1, z2, sel);
                acc01 = hadd2(acc01, p01);
                acc23 = hadd2(acc23, p23);
                ap[nt >> 1][(nt & 1) * 2 + 0] = p01;
                ap[nt >> 1][(nt & 1) * 2 + 1] = p23;
            }
            // PV for this quad's 32 kv columns (kt = qd*2, qd*2+1)
#pragma unroll
            for (int j = 0; j < 2; j++) {
                int kt = qd * 2 + j;
                uint32_t vb[4];
                uint32_t base = vb_base + (uint32_t)kt * (16 * 80) + v_lane_off;
                ldsm_x4_t(vb, base);
                mma_h(of[0], ap[j], vb);
                mma_h(of[1], ap[j], vb + 2);
                ldsm_x4_t(vb, base + 32);
                mma_h(of[2], ap[j], vb);
                mma_h(of[3], ap[j], vb + 2);
            }
        }
        // flush per-tile row sums to fp32
        {
            float2 f0 = h2_to_f2(acc01);
            float2 f1 = h2_to_f2(acc23);
            ls0 += f0.x + f0.y;
            ls1 += f1.x + f1.y;
        }
        __syncthreads();
    }

    // quad-reduce row sums
    ls0 += __shfl_xor_sync(0xFFFFFFFFu, ls0, 1);
    ls0 += __shfl_xor_sync(0xFFFFFFFFu, ls0, 2);
    ls1 += __shfl_xor_sync(0xFFFFFFFFu, ls1, 1);
    ls1 += __shfl_xor_sync(0xFFFFFFFFu, ls1, 2);

    // write partial O (fp32, unnormalized) + partial l
    float* p0 = g_pO + (size_t)z * NN * DD + (size_t)row0 * DD + h * HD + 2 * tig;
    float* p1 = p0 + 8 * DD;
#pragma unroll
    for (int v = 0; v < 4; v++) {
        *(float2*)(p0 + v * 8) = h2_to_f2(of[v][0]);
        *(float2*)(p1 + v * 8) = h2_to_f2(of[v][1]);
    }
    if (tig == 0) {
        g_pl[z * HH * NN + h * NN + row0] = ls0;
        g_pl[z * HH * NN + h * NN + row0 + 8] = ls1;
    }
}

// ================= combine split-KV partials -> bf16 attended =============
__global__ void __launch_bounds__(256) combine_kernel() {
    int i = (blockIdx.x * 256 + threadIdx.x) * 4;   // over NN*DD
    int n = i >> 8;            // DD = 256
    int c = i & 255;
    int h = c >> 5;
    float l = g_pl[h * NN + n] + g_pl[HH * NN + h * NN + n];
    float inv = 1.f / l;
    float4 a = *(const float4*)(g_pO + i);
    float4 b = *(const float4*)(g_pO + NN * DD + i);
    *(uint2*)(g_attb + i) = make_uint2(
        pack_bf16x2((a.x + b.x) * inv, (a.y + b.y) * inv),
        pack_bf16x2((a.z + b.z) * inv, (a.w + b.w) * inv));
}

// ================= residual + LayerNorm (warp-shuffle) =================
__global__ void ln_kernel(const float* __restrict__ tmp,
                          const float* __restrict__ x,
                          const float* __restrict__ w,
                          const float* __restrict__ b,
                          float* __restrict__ out) {
    int n = blockIdx.x;
    int tid = threadIdx.x;  // 256 == DD
    int wid = tid >> 5, lane = tid & 31;
    float v = tmp[n * DD + tid] + x[n * DD + tid];
    float s1 = v, s2 = v * v;
#pragma unroll
    for (int o = 16; o > 0; o >>= 1) {
        s1 += __shfl_xor_sync(0xFFFFFFFFu, s1, o);
        s2 += __shfl_xor_sync(0xFFFFFFFFu, s2, o);
    }
    __shared__ float a1[8], a2[8];
    if (lane == 0) { a1[wid] = s1; a2[wid] = s2; }
    __syncthreads();
    float t1 = 0.f, t2 = 0.f;
#pragma unroll
    for (int i = 0; i < 8; i++) { t1 += a1[i]; t2 += a2[i]; }
    float mu = t1 * (1.f / 256.f);
    float var = t2 * (1.f / 256.f) - mu * mu;
    float inv = rsqrtf(var + 1e-5f);
    out[n * DD + tid] = (v - mu) * inv * w[tid] + b[tid];
}

// ================= launch =================
extern "C" void kernel_launch(void* const* d_in, const int* in_sizes, int n_in,
                              void* d_out, int out_size) {
    const float* x   = (const float*)d_in[0];
    const int*   ei  = (const int*)d_in[1];
    const float* Wq  = (const float*)d_in[2];
    const float* bq  = (const float*)d_in[3];
    const float* Wk  = (const float*)d_in[4];
    const float* bk  = (const float*)d_in[5];
    const float* Wv  = (const float*)d_in[6];
    const float* bv  = (const float*)d_in[7];
    const float* Wo  = (const float*)d_in[8];
    const float* bo  = (const float*)d_in[9];
    const float* lnw = (const float*)d_in[10];
    const float* lnb = (const float*)d_in[11];
    float* out = (float*)d_out;

    float* gT;
    cudaGetSymbolAddress((void**)&gT, g_tmp);

    // K1: casts ∥ adjacency init
    k1_kernel<<<3328, 256>>>(x, Wq, Wk, Wv, Wo);
    // K2: QKV projections ∥ edge scatter
    k2_kernel<<<dim3(DD / 128, NN / 64, 4), 128>>>(ei, bq, bk, bv);
    // reach-2 mask
    mask_kernel<<<NN, 256>>>();
    // tensor-core attention, split-KV 2-way, 4 CTAs/SM
    attn_kernel<<<dim3(NN / 128, HH, NSPLIT), 256>>>();
    // combine partials
    combine_kernel<<<NN * DD / 1024, 256>>>();
    // output projection (tensor core, fp32 out) + residual + LN
    wo_gemm_kernel<<<dim3(DD / 128, NN / 64), 128>>>(bo);
    ln_kernel<<<NN, 256>>>(gT, x, lnw, lnb, out);
}

// round 14
// speedup vs baseline: 1.0244x; 1.0051x over previous
#include <cuda_runtime.h>
#include <cuda_bf16.h>
#include <cuda_fp16.h>
#include <math.h>
#include <stdint.h>

// ---------------- problem constants ----------------
#define NN 4096
#define DD 256
#define HH 8
#define HD 32
#define EE 65536
#define NWORDS 128
// (1/sqrt(32)) * log2(e): folded into Q so softmax weight = exp2(S)
#define QSCALE 0.25503486f
#define NSPLIT 2
#define TILES_PER_SPLIT 16

// ---------------- scratch globals (no allocs allowed) ----------------
__device__ uint32_t g_adj[NN * NWORDS];
__device__ uint32_t g_mask[NN * NWORDS];
__device__ __nv_bfloat16 g_xb[NN * DD];
__device__ __nv_bfloat16 g_Wb[4 * DD * DD];   // Wq, Wk, Wv, Wo (bf16)
__device__ __half g_Qh[NN * DD];              // fp16, pre-scaled by QSCALE
__device__ __half g_Kh[NN * DD];
__device__ __half g_Vh[NN * DD];
__device__ __nv_bfloat16 g_attb[NN * DD];     // attention output (bf16)
__device__ float g_pO[NSPLIT * NN * DD];      // split-KV partial O (unnormalized)
__device__ float g_pl[NSPLIT * HH * NN];      // split-KV partial row sums

// ---------------- PTX helpers ----------------
__device__ __forceinline__ uint32_t smem_u32(const void* p) {
    uint32_t a;
    asm("{ .reg .u64 t; cvta.to.shared.u64 t, %1; cvt.u32.u64 %0, t; }"
        : "=r"(a) : "l"(p));
    return a;
}
__device__ __forceinline__ uint32_t pack_bf16x2(float lo, float hi) {
    uint32_t r;
    asm("cvt.rn.bf16x2.f32 %0, %1, %2;" : "=r"(r) : "f"(hi), "f"(lo));
    return r;
}
__device__ __forceinline__ uint32_t pack_f16x2(float lo, float hi) {
    uint32_t r;
    asm("cvt.rn.f16x2.f32 %0, %1, %2;" : "=r"(r) : "f"(hi), "f"(lo));
    return r;
}
__device__ __forceinline__ uint32_t ex2_f16x2(uint32_t x) {
    uint32_t y;
    asm("ex2.approx.f16x2 %0, %1;" : "=r"(y) : "r"(x));
    return y;
}
__device__ __forceinline__ uint32_t hadd2(uint32_t a, uint32_t b) {
    uint32_t d;
    asm("add.rn.f16x2 %0, %1, %2;" : "=r"(d) : "r"(a), "r"(b));
    return d;
}
__device__ __forceinline__ uint32_t prmt(uint32_t a, uint32_t b, uint32_t sel) {
    uint32_t d;
    asm("prmt.b32 %0, %1, %2, %3;" : "=r"(d) : "r"(a), "r"(b), "r"(sel));
    return d;
}
__device__ __forceinline__ float2 h2_to_f2(uint32_t u) {
    __half2 h = *reinterpret_cast<__half2*>(&u);
    return __half22float2(h);
}
__device__ __forceinline__ void ldsm_x4(uint32_t* r, uint32_t addr) {
    asm volatile("ldmatrix.sync.aligned.m8n8.x4.shared.b16 {%0,%1,%2,%3}, [%4];"
        : "=r"(r[0]), "=r"(r[1]), "=r"(r[2]), "=r"(r[3]) : "r"(addr));
}
__device__ __forceinline__ void ldsm_x4_t(uint32_t* r, uint32_t addr) {
    asm volatile("ldmatrix.sync.aligned.m8n8.x4.trans.shared.b16 {%0,%1,%2,%3}, [%4];"
        : "=r"(r[0]), "=r"(r[1]), "=r"(r[2]), "=r"(r[3]) : "r"(addr));
}
__device__ __forceinline__ void mma_bf16(float* c, const uint32_t* a, const uint32_t* b) {
    asm volatile(
        "mma.sync.aligned.m16n8k16.row.col.f32.bf16.bf16.f32 "
        "{%0,%1,%2,%3}, {%4,%5,%6,%7}, {%8,%9}, {%0,%1,%2,%3};"
        : "+f"(c[0]), "+f"(c[1]), "+f"(c[2]), "+f"(c[3])
        : "r"(a[0]), "r"(a[1]), "r"(a[2]), "r"(a[3]), "r"(b[0]), "r"(b[1]));
}
// fp16 in, fp16 accumulate
__device__ __forceinline__ void mma_h(uint32_t* d, const uint32_t* a, const uint32_t* b) {
    asm volatile(
        "mma.sync.aligned.m16n8k16.row.col.f16.f16.f16.f16 "
        "{%0,%1}, {%2,%3,%4,%5}, {%6,%7}, {%0,%1};"
        : "+r"(d[0]), "+r"(d[1])
        : "r"(a[0]), "r"(a[1]), "r"(a[2]), "r"(a[3]), "r"(b[0]), "r"(b[1]));
}
__device__ __forceinline__ void cp16(uint32_t dst, const void* src) {
    asm volatile("cp.async.cg.shared.global [%0], [%1], 16;" :: "r"(dst), "l"(src));
}
#define CP_COMMIT() asm volatile("cp.async.commit_group;" ::: "memory")
#define CP_WAIT(n)  asm volatile("cp.async.wait_group %0;" :: "n"(n) : "memory")

// ================= K1: bf16 casts  ∥  adjacency init (one launch) =========
__global__ void __launch_bounds__(256) k1_kernel(const float* __restrict__ x,
                                                 const float* __restrict__ Wq,
                                                 const float* __restrict__ Wk,
                                                 const float* __restrict__ Wv,
                                                 const float* __restrict__ Wo) {
    int b = blockIdx.x;
    if (b < 1280) {
        int i = (b * 256 + threadIdx.x) * 4;
        const float* src;
        __nv_bfloat16* dst;
        if (i < NN * DD) {
            src = x + i; dst = g_xb + i;
        } else {
            int j = i - NN * DD;
            int w = j >> 16;
            int o = j & 65535;
            src = ((w == 0) ? Wq : (w == 1) ? Wk : (w == 2) ? Wv : Wo) + o;
            dst = g_Wb + w * (DD * DD) + o;
        }
        float4 v = *(const float4*)src;
        *(uint2*)dst = make_uint2(pack_bf16x2(v.x, v.y), pack_bf16x2(v.z, v.w));
    } else {
        int idx = (b - 1280) * 256 + threadIdx.x;
        int n = idx >> 7, w = idx & 127;
        uint32_t v = 0;
        if (w == (n >> 5)) v = 1u << (n & 31);
        g_adj[idx] = v;
    }
}

// ================= bf16 tensor-core GEMM core (QKV; 64x128 tile) =========
__device__ __forceinline__ void gemm_core(const __nv_bfloat16* __restrict__ A,
                                          const __nv_bfloat16* __restrict__ W,
                                          const float* __restrict__ bias,
                                          __half* __restrict__ Cv, float scale) {
    __shared__ __nv_bfloat16 sA[2][64 * 40];
    __shared__ __nv_bfloat16 sB[2][32 * 136];

    const int tid = threadIdx.x;
    const int wid = tid >> 5;
    const int lane = tid & 31;
    const int m0 = blockIdx.y * 64;
    const int n0 = blockIdx.x * 128;

    const uint32_t aA = smem_u32(sA);
    const uint32_t aB = smem_u32(sB);
    const char* Abase = (const char*)A + (size_t)m0 * (DD * 2);
    const char* Bbase = (const char*)W + (size_t)n0 * 2;

    {
#pragma unroll
        for (int j = 0; j < 2; j++) {
            int t = tid + j * 128;
            int r = t >> 2, c = t & 3;
            cp16(aA + r * 80 + c * 16, Abase + (size_t)r * 512 + c * 16);
        }
#pragma unroll
        for (int j = 0; j < 4; j++) {
            int t = tid + j * 128;
            int r = t >> 4, c = t & 15;
            cp16(aB + r * 272 + c * 16, Bbase + (size_t)r * 512 + c * 16);
        }
        CP_COMMIT();
    }

    float acc[16][4];
#pragma unroll
    for (int j = 0; j < 16; j++)
        acc[j][0] = acc[j][1] = acc[j][2] = acc[j][3] = 0.f;

    const int m = lane >> 3, rr = lane & 7;
    const uint32_t a_off = (uint32_t)((wid * 16 + (m & 1) * 8 + rr) * 80 + (m >> 1) * 16);
    const uint32_t b_lane = (uint32_t)(((lane >> 3) & 1) * 8 * 272 + (lane & 7) * 272 +
                                       (lane >> 4) * 16);

    for (int t = 0; t < 8; t++) {
        if (t < 7) {
            int nb = (t + 1) & 1;
            uint32_t dA = aA + (uint32_t)nb * 5120;
            uint32_t dB = aB + (uint32_t)nb * 8704;
            const char* As = Abase + (size_t)(t + 1) * 64;
            const char* Bs = Bbase + (size_t)(t + 1) * 32 * 512;
#pragma unroll
            for (int j = 0; j < 2; j++) {
                int u = tid + j * 128;
                int r = u >> 2, c = u & 3;
                cp16(dA + r * 80 + c * 16, As + (size_t)r * 512 + c * 16);
            }
#pragma unroll
            for (int j = 0; j < 4; j++) {
                int u = tid + j * 128;
                int r = u >> 4, c = u & 15;
                cp16(dB + r * 272 + c * 16, Bs + (size_t)r * 512 + c * 16);
            }
            CP_COMMIT();
            CP_WAIT(1);
        } else {
            CP_WAIT(0);
        }
        __syncthreads();

        const uint32_t bufA = aA + (uint32_t)(t & 1) * 5120;
        const uint32_t bufB = aB + (uint32_t)(t & 1) * 8704;

        uint32_t aq[2][4];
        ldsm_x4(aq[0], bufA + a_off);
        ldsm_x4(aq[1], bufA + a_off + 32);

#pragma unroll
        for (int ks = 0; ks < 2; ks++) {
#pragma unroll
            for (int j = 0; j < 8; j++) {
                uint32_t vb[4];
                ldsm_x4_t(vb, bufB + (uint32_t)(ks * 16 * 272 + j * 32) + b_lane);
                mma_bf16(acc[2 * j],     aq[ks], vb);
                mma_bf16(acc[2 * j + 1], aq[ks], vb + 2);
            }
        }
        __syncthreads();
    }

    const int gg = lane >> 2, tig = lane & 3;
    const int r0 = m0 + wid * 16 + gg;
#pragma unroll
    for (int j = 0; j < 16; j++) {
        int col = n0 + j * 8 + 2 * tig;
        float2 b2 = __ldg((const float2*)(bias + col));
        *(uint32_t*)(Cv + (size_t)r0 * DD + col) =
            pack_f16x2((acc[j][0] + b2.x) * scale, (acc[j][1] + b2.y) * scale);
        *(uint32_t*)(Cv + (size_t)(r0 + 8) * DD + col) =
            pack_f16x2((acc[j][2] + b2.x) * scale, (acc[j][3] + b2.y) * scale);
    }
}

// ================= K2: QKV projections  ∥  edge scatter (one launch) ======
__global__ void __launch_bounds__(128) k2_kernel(const int* __restrict__ ei,
                                                 const float* __restrict__ bq,
                                                 const float* __restrict__ bk,
                                                 const float* __restrict__ bv) {
    int z = blockIdx.z;
    if (z < 3) {
        const float* bias = (z == 0) ? bq : (z == 1) ? bk : bv;
        __half* C = (z == 0) ? g_Qh : (z == 1) ? g_Kh : g_Vh;
        float scale = (z == 0) ? QSCALE : 1.f;
        gemm_core(g_xb, g_Wb + (size_t)z * DD * DD, bias, C, scale);
    } else {
        int bid = blockIdx.x + blockIdx.y * 2;            // 0..127
        int e = (bid * 128 + threadIdx.x) * 4;            // 4 edges/thread
        uint4 s4 = *(const uint4*)(ei + e);
        uint4 d4 = *(const uint4*)(ei + EE + e);
        atomicOr(&g_adj[s4.x * NWORDS + (d4.x >> 5)], 1u << (d4.x & 31));
        atomicOr(&g_adj[d4.x * NWORDS + (s4.x >> 5)], 1u << (s4.x & 31));
        atomicOr(&g_adj[s4.y * NWORDS + (d4.y >> 5)], 1u << (d4.y & 31));
        atomicOr(&g_adj[d4.y * NWORDS + (s4.y >> 5)], 1u << (s4.y & 31));
        atomicOr(&g_adj[s4.z * NWORDS + (d4.z >> 5)], 1u << (d4.z & 31));
        atomicOr(&g_adj[d4.z * NWORDS + (s4.z >> 5)], 1u << (s4.z & 31));
        atomicOr(&g_adj[s4.w * NWORDS + (d4.w >> 5)], 1u << (d4.w & 31));
        atomicOr(&g_adj[d4.w * NWORDS + (s4.w >> 5)], 1u << (s4.w & 31));
    }
}

// ================= reach-2 mask (split neighbor list across 2 halves) =====
__global__ void __launch_bounds__(256) mask_kernel() {
    int n = blockIdx.x;
    int tid = threadIdx.x;
    int w = tid & 127;
    int h = tid >> 7;
    int lane = tid & 31;
    __shared__ uint16_t nbr[1024];
    __shared__ int cnt;
    __shared__ uint32_t accs[128];
    if (tid == 0) cnt = 0;
    __syncthreads();

    if (tid < 128) {
        uint32_t bits = g_adj[n * NWORDS + tid];
        int pc = __popc(bits);
        int pref = pc;
#pragma unroll
        for (int o = 1; o < 32; o <<= 1) {
            int v = __shfl_up_sync(0xFFFFFFFFu, pref, o);
            if (lane >= o) pref += v;
        }
        int wtot = __shfl_sync(0xFFFFFFFFu, pref, 31);
        int wbase = 0;
        if (lane == 0) wbase = atomicAdd(&cnt, wtot);
        wbase = __shfl_sync(0xFFFFFFFFu, wbase, 0);
        int off = wbase + pref - pc;
        while (bits) {
            int b = __ffs(bits) - 1;
            bits &= bits - 1;
            nbr[off++] = (uint16_t)((tid << 5) + b);
        }
    }
    __syncthreads();

    int c = cnt;
    uint32_t acc = 0;
    int i = h;
    for (; i + 6 < c; i += 8) {
        uint32_t a0 = g_adj[(int)nbr[i + 0] * NWORDS + w];
        uint32_t a1 = g_adj[(int)nbr[i + 2] * NWORDS + w];
        uint32_t a2 = g_adj[(int)nbr[i + 4] * NWORDS + w];
        uint32_t a3 = g_adj[(int)nbr[i + 6] * NWORDS + w];
        acc |= (a0 | a1) | (a2 | a3);
    }
    for (; i < c; i += 2)
        acc |= g_adj[(int)nbr[i] * NWORDS + w];

    if (h == 0) accs[w] = acc;
    __syncthreads();
    if (h == 1) g_mask[n * NWORDS + w] = accs[w] | acc;
}

// ================= attention: split-KV, 4 CTAs/SM =========================
struct AttnSmemH {
    __half Qs[128 * 32];       // 8192 B (64B rows)
    __half Ks[2][128 * 40];    // 2 x 10240 B
    __half Vs[2][128 * 40];    // 2 x 10240 B
};                             // total 49152 B

__global__ void __launch_bounds__(256, 4) attn_kernel() {
    __shared__ AttnSmemH sm;
    const int tid = threadIdx.x;
    const int wid = tid >> 5;
    const int lane = tid & 31;
    const int h = blockIdx.y;
    const int q0 = blockIdx.x * 128;
    const int z = blockIdx.z;
    const int t0 = z * TILES_PER_SPLIT;
    const int t1 = t0 + TILES_PER_SPLIT;

    const uint32_t s_q = smem_u32(sm.Qs);
    const uint32_t s_k0 = smem_u32(sm.Ks[0]);
    const uint32_t s_v0 = smem_u32(sm.Vs[0]);

    const char* ksrc = (const char*)(g_Kh + h * HD);
    const char* vsrc = (const char*)(g_Vh + h * HD);

    // ---- prologue: Q + K(t0)/V(t0) via cp.async ----
    {
        const char* qsrc = (const char*)(g_Qh + (size_t)q0 * DD + h * HD);
        size_t tb = (size_t)t0 * 128 * 512;
#pragma unroll
        for (int j = 0; j < 2; j++) {
            int chunk = tid + j * 256;
            int r = chunk >> 2, c = chunk & 3;
            cp16(s_q + (uint32_t)(r * 64 + c * 16), qsrc + (size_t)r * 512 + c * 16);
        }
#pragma unroll
        for (int j = 0; j < 2; j++) {
            int chunk = tid + j * 256;
            int r = chunk >> 2, c = chunk & 3;
            uint32_t off = (uint32_t)(r * 80 + c * 16);
            size_t gs = tb + (size_t)r * 512 + c * 16;
            cp16(s_k0 + off, ksrc + gs);
            cp16(s_v0 + off, vsrc + gs);
        }
        CP_COMMIT();
    }

    const int wq0 = wid * 16;
    const int g = lane >> 2, tig = lane & 3;
    const int row0 = q0 + wq0 + g;
    const uint32_t* mrow_lo = g_mask + (size_t)row0 * NWORDS;
    const uint32_t* mrow_hi = g_mask + (size_t)(row0 + 8) * NWORDS;

    CP_WAIT(0);
    __syncthreads();

    uint32_t aq[2][4];
    {
        int m = lane >> 3, rr = lane & 7;
        uint32_t base = s_q + (uint32_t)((wq0 + (m & 1) * 8 + rr) * 64 + (m >> 1) * 16);
        ldsm_x4(aq[0], base);
        ldsm_x4(aq[1], base + 32);
    }

    uint32_t of[4][2];
#pragma unroll
    for (int v = 0; v < 4; v++) { of[v][0] = 0u; of[v][1] = 0u; }
    float ls0 = 0.f, ls1 = 0.f;

    const uint32_t k_lane_off = (uint32_t)((lane & 7) * 80 + (lane >> 3) * 16);
    const uint32_t v_lane_off = (uint32_t)(((lane >> 3) & 1) * 8 * 80 + (lane & 7) * 80 +
                                           (lane >> 4) * 16);

    for (int t = t0; t < t1; t++) {
        int buf = t & 1;
        if (t < t1 - 1) {
            int nb = (t + 1) & 1;
            uint32_t skb = s_k0 + (uint32_t)nb * 10240;
            uint32_t svb = s_v0 + (uint32_t)nb * 10240;
            size_t tb = (size_t)(t + 1) * 128 * 512;
#pragma unroll
            for (int j = 0; j < 2; j++) {
                int chunk = tid + j * 256;
                int r = chunk >> 2, c = chunk & 3;
                uint32_t off = (uint32_t)(r * 80 + c * 16);
                size_t gs = tb + (size_t)r * 512 + c * 16;
                cp16(skb + off, ksrc + gs);
                cp16(svb + off, vsrc + gs);
            }
            CP_COMMIT();
            CP_WAIT(1);
        } else {
            CP_WAIT(0);
        }
        uint4 mw_lo = __ldg((const uint4*)(mrow_lo + t * 4));
        uint4 mw_hi = __ldg((const uint4*)(mrow_hi + t * 4));
        __syncthreads();

        const uint32_t kb_base = s_k0 + (uint32_t)buf * 10240;
        const uint32_t vb_base = s_v0 + (uint32_t)buf * 10240;
        const uint32_t mwl[4] = {mw_lo.x, mw_lo.y, mw_lo.z, mw_lo.w};
        const uint32_t mwh[4] = {mw_hi.x, mw_hi.y, mw_hi.z, mw_hi.w};

        uint32_t acc01 = 0, acc23 = 0;
#pragma unroll
        for (int qd = 0; qd < 4; qd++) {
            uint32_t kb[4][4];
#pragma unroll
            for (int nt = 0; nt < 4; nt++)
                ldsm_x4(kb[nt], kb_base + (uint32_t)((qd * 4 + nt) * (8 * 80)) + k_lane_off);
            uint32_t w0 = mwl[qd] >> (2 * tig);
            uint32_t w1 = mwh[qd] >> (2 * tig);
            uint32_t y1 = (w0 & 0x01010101u) << 7;
            uint32_t y2 = (w0 & 0x02020202u) << 6;
            uint32_t z1 = (w1 & 0x01010101u) << 7;
            uint32_t z2 = (w1 & 0x02020202u) << 6;
            uint32_t ap[2][4];
#pragma unroll
            for (int nt = 0; nt < 4; nt++) {
                uint32_t sd[2] = {0u, 0u};
                mma_h(sd, aq[0], kb[nt]);
                mma_h(sd, aq[1], kb[nt] + 2);
                uint32_t sel = 0xCC88u + (uint32_t)nt * 0x1111u;
                uint32_t p01 = ex2_f16x2(sd[0]) & prmt(y1, y2, sel);
                uint32_t p23 = ex2_f16x2(sd[1]) & prmt(z1, z2, sel);
                acc01 = hadd2(acc01, p01);
                acc23 = hadd2(acc23, p23);
                ap[nt >> 1][(nt & 1) * 2 + 0] = p01;
                ap[nt >> 1][(nt & 1) * 2 + 1] = p23;
            }
#pragma unroll
            for (int j = 0; j < 2; j++) {
                int kt = qd * 2 + j;
                uint32_t vb[4];
                uint32_t base = vb_base + (uint32_t)kt * (16 * 80) + v_lane_off;
                ldsm_x4_t(vb, base);
                mma_h(of[0], ap[j], vb);
                mma_h(of[1], ap[j], vb + 2);
                ldsm_x4_t(vb, base + 32);
                mma_h(of[2], ap[j], vb);
                mma_h(of[3], ap[j], vb + 2);
            }
        }
        {
            float2 f0 = h2_to_f2(acc01);
            float2 f1 = h2_to_f2(acc23);
            ls0 += f0.x + f0.y;
            ls1 += f1.x + f1.y;
        }
        __syncthreads();
    }

    ls0 += __shfl_xor_sync(0xFFFFFFFFu, ls0, 1);
    ls0 += __shfl_xor_sync(0xFFFFFFFFu, ls0, 2);
    ls1 += __shfl_xor_sync(0xFFFFFFFFu, ls1, 1);
    ls1 += __shfl_xor_sync(0xFFFFFFFFu, ls1, 2);

    float* p0 = g_pO + (size_t)z * NN * DD + (size_t)row0 * DD + h * HD + 2 * tig;
    float* p1 = p0 + 8 * DD;
#pragma unroll
    for (int v = 0; v < 4; v++) {
        *(float2*)(p0 + v * 8) = h2_to_f2(of[v][0]);
        *(float2*)(p1 + v * 8) = h2_to_f2(of[v][1]);
    }
    if (tig == 0) {
        g_pl[z * HH * NN + h * NN + row0] = ls0;
        g_pl[z * HH * NN + h * NN + row0 + 8] = ls1;
    }
}

// ================= combine split-KV partials -> bf16 attended =============
__global__ void __launch_bounds__(256) combine_kernel() {
    int i = (blockIdx.x * 256 + threadIdx.x) * 4;   // over NN*DD
    int n = i >> 8;            // DD = 256
    int c = i & 255;
    int h = c >> 5;
    float l = g_pl[h * NN + n] + g_pl[HH * NN + h * NN + n];
    float inv = 1.f / l;
    float4 a = *(const float4*)(g_pO + i);
    float4 b = *(const float4*)(g_pO + NN * DD + i);
    *(uint2*)(g_attb + i) = make_uint2(
        pack_bf16x2((a.x + b.x) * inv, (a.y + b.y) * inv),
        pack_bf16x2((a.z + b.z) * inv, (a.w + b.w) * inv));
}

// ================= fused Wo GEMM + residual + LayerNorm ====================
// CTA tile 64 rows x 256 cols (full feature dim). grid 64, 256 thr / 8 warps.
// Warp = 16 rows x 128 cols: rgrp = wid&3, cgrp = wid>>2.
__global__ void __launch_bounds__(256) wo_ln_kernel(const float* __restrict__ bo,
                                                    const float* __restrict__ x,
                                                    const float* __restrict__ lnw,
                                                    const float* __restrict__ lnb,
                                                    float* __restrict__ out) {
    __shared__ __nv_bfloat16 sA[2][64 * 40];     // 2 x 5120 B
    __shared__ __nv_bfloat16 sB[2][32 * 264];    // 2 x 16896 B (528B rows)
    __shared__ float sW[256], sBb[256];
    __shared__ float s1buf[2][64], s2buf[2][64];

    const int tid = threadIdx.x;
    const int wid = tid >> 5;
    const int lane = tid & 31;
    const int m0 = blockIdx.x * 64;
    const int rgrp = wid & 3;
    const int cgrp = wid >> 2;

    const uint32_t aA = smem_u32(sA);
    const uint32_t aB = smem_u32(sB);
    const char* Abase = (const char*)g_attb + (size_t)m0 * (DD * 2);
    const char* Bbase = (const char*)(g_Wb + (size_t)3 * DD * DD);

    sW[tid] = lnw[tid];
    sBb[tid] = lnb[tid];

    // stage 0
    {
        int r = tid >> 2, c = tid & 3;   // A: 256 chunks
        cp16(aA + r * 80 + c * 16, Abase + (size_t)r * 512 + c * 16);
#pragma unroll
        for (int j = 0; j < 4; j++) {    // B: 1024 chunks
            int u = tid + j * 256;
            int br = u >> 5, bc = u & 31;
            cp16(aB + br * 528 + bc * 16, Bbase + (size_t)br * 512 + bc * 16);
        }
        CP_COMMIT();
    }

    float acc[16][4];
#pragma unroll
    for (int j = 0; j < 16; j++)
        acc[j][0] = acc[j][1] = acc[j][2] = acc[j][3] = 0.f;

    const int m = lane >> 3, rr = lane & 7;
    const uint32_t a_off = (uint32_t)((rgrp * 16 + (m & 1) * 8 + rr) * 80 + (m >> 1) * 16);
    const uint32_t b_lane = (uint32_t)(((lane >> 3) & 1) * 8 * 528 + (lane & 7) * 528 +
                                       (lane >> 4) * 16);

    for (int t = 0; t < 8; t++) {
        if (t < 7) {
            int nb = (t + 1) & 1;
            uint32_t dA = aA + (uint32_t)nb * 5120;
            uint32_t dB = aB + (uint32_t)nb * 16896;
            const char* As = Abase + (size_t)(t + 1) * 64;
            const char* Bs = Bbase + (size_t)(t + 1) * 32 * 512;
            {
                int r = tid >> 2, c = tid & 3;
                cp16(dA + r * 80 + c * 16, As + (size_t)r * 512 + c * 16);
            }
#pragma unroll
            for (int j = 0; j < 4; j++) {
                int u = tid + j * 256;
                int br = u >> 5, bc = u & 31;
                cp16(dB + br * 528 + bc * 16, Bs + (size_t)br * 512 + bc * 16);
            }
            CP_COMMIT();
            CP_WAIT(1);
        } else {
            CP_WAIT(0);
        }
        __syncthreads();

        const uint32_t bufA = aA + (uint32_t)(t & 1) * 5120;
        const uint32_t bufB = aB + (uint32_t)(t & 1) * 16896;

        uint32_t aq[2][4];
        ldsm_x4(aq[0], bufA + a_off);
        ldsm_x4(aq[1], bufA + a_off + 32);

#pragma unroll
        for (int ks = 0; ks < 2; ks++) {
#pragma unroll
            for (int j = 0; j < 8; j++) {
                uint32_t vb[4];
                ldsm_x4_t(vb, bufB + (uint32_t)(ks * 16 * 528 + cgrp * 256 + j * 32) + b_lane);
                mma_bf16(acc[2 * j],     aq[ks], vb);
                mma_bf16(acc[2 * j + 1], aq[ks], vb + 2);
            }
        }
        __syncthreads();
    }

    // ---- epilogue: +bo +x, row stats, LN, store ----
    const int g = lane >> 2, tig = lane & 3;
    const int rloc0 = rgrp * 16 + g;          // 0..63
    const int rloc1 = rloc0 + 8;
    const int r0 = m0 + rloc0;
    float s1a = 0.f, s2a = 0.f, s1b = 0.f, s2b = 0.f;
#pragma unroll
    for (int j = 0; j < 16; j++) {
        int col = cgrp * 128 + j * 8 + 2 * tig;
        float2 b2 = __ldg((const float2*)(bo + col));
        float2 xa = __ldg((const float2*)(x + (size_t)r0 * DD + col));
        float2 xb = __ldg((const float2*)(x + (size_t)(r0 + 8) * DD + col));
        float v0 = acc[j][0] + b2.x + xa.x;
        float v1 = acc[j][1] + b2.y + xa.y;
        float v2 = acc[j][2] + b2.x + xb.x;
        float v3 = acc[j][3] + b2.y + xb.y;
        acc[j][0] = v0; acc[j][1] = v1; acc[j][2] = v2; acc[j][3] = v3;
        s1a += v0 + v1; s2a += v0 * v0 + v1 * v1;
        s1b += v2 + v3; s2b += v2 * v2 + v3 * v3;
    }
    s1a += __shfl_xor_sync(0xFFFFFFFFu, s1a, 1);
    s1a += __shfl_xor_sync(0xFFFFFFFFu, s1a, 2);
    s2a += __shfl_xor_sync(0xFFFFFFFFu, s2a, 1);
    s2a += __shfl_xor_sync(0xFFFFFFFFu, s2a, 2);
    s1b += __shfl_xor_sync(0xFFFFFFFFu, s1b, 1);
    s1b += __shfl_xor_sync(0xFFFFFFFFu, s1b, 2);
    s2b += __shfl_xor_sync(0xFFFFFFFFu, s2b, 1);
    s2b += __shfl_xor_sync(0xFFFFFFFFu, s2b, 2);
    if (tig == 0) {
        s1buf[cgrp][rloc0] = s1a; s2buf[cgrp][rloc0] = s2a;
        s1buf[cgrp][rloc1] = s1b; s2buf[cgrp][rloc1] = s2b;
    }
    __syncthreads();
    float mu0 = (s1buf[0][rloc0] + s1buf[1][rloc0]) * (1.f / 256.f);
    float va0 = (s2buf[0][rloc0] + s2buf[1][rloc0]) * (1.f / 256.f) - mu0 * mu0;
    float inv0 = rsqrtf(va0 + 1e-5f);
    float mu1 = (s1buf[0][rloc1] + s1buf[1][rloc1]) * (1.f / 256.f);
    float va1 = (s2buf[0][rloc1] + s2buf[1][rloc1]) * (1.f / 256.f) - mu1 * mu1;
    float inv1 = rsqrtf(va1 + 1e-5f);
#pragma unroll
    for (int j = 0; j < 16; j++) {
        int col = cgrp * 128 + j * 8 + 2 * tig;
        float w0 = sW[col], w1 = sW[col + 1];
        float c0 = sBb[col], c1 = sBb[col + 1];
        *(float2*)(out + (size_t)r0 * DD + col) =
            make_float2((acc[j][0] - mu0) * inv0 * w0 + c0,
                        (acc[j][1] - mu0) * inv0 * w1 + c1);
        *(float2*)(out + (size_t)(r0 + 8) * DD + col) =
            make_float2((acc[j][2] - mu1) * inv1 * w0 + c0,
                        (acc[j][3] - mu1) * inv1 * w1 + c1);
    }
}

// ================= launch =================
extern "C" void kernel_launch(void* const* d_in, const int* in_sizes, int n_in,
                              void* d_out, int out_size) {
    const float* x   = (const float*)d_in[0];
    const int*   ei  = (const int*)d_in[1];
    const float* Wq  = (const float*)d_in[2];
    const float* bq  = (const float*)d_in[3];
    const float* Wk  = (const float*)d_in[4];
    const float* bk  = (const float*)d_in[5];
    const float* Wv  = (const float*)d_in[6];
    const float* bv  = (const float*)d_in[7];
    const float* Wo  = (const float*)d_in[8];
    const float* bo  = (const float*)d_in[9];
    const float* lnw = (const float*)d_in[10];
    const float* lnb = (const float*)d_in[11];
    float* out = (float*)d_out;

    // K1: casts ∥ adjacency init
    k1_kernel<<<3328, 256>>>(x, Wq, Wk, Wv, Wo);
    // K2: QKV projections ∥ edge scatter
    k2_kernel<<<dim3(DD / 128, NN / 64, 4), 128>>>(ei, bq, bk, bv);
    // reach-2 mask
    mask_kernel<<<NN, 256>>>();
    // tensor-core attention, split-KV 2-way, 4 CTAs/SM
    attn_kernel<<<dim3(NN / 128, HH, NSPLIT), 256>>>();
    // combine partials
    combine_kernel<<<NN * DD / 1024, 256>>>();
    // fused Wo GEMM + residual + LayerNorm
    wo_ln_kernel<<<NN / 64, 256>>>(bo, x, lnw, lnb, out);
}

// round 15
// speedup vs baseline: 1.0778x; 1.0522x over previous
#include <cuda_runtime.h>
#include <cuda_bf16.h>
#include <cuda_fp16.h>
#include <math.h>
#include <stdint.h>

// ---------------- problem constants ----------------
#define NN 4096
#define DD 256
#define HH 8
#define HD 32
#define EE 65536
#define NWORDS 128
// (1/sqrt(32)) * log2(e): folded into Q so softmax weight = exp2(S)
#define QSCALE 0.25503486f
#define NSPLIT 4
#define TILES_PER_SPLIT 8

// ---------------- scratch globals (no allocs allowed) ----------------
__device__ uint32_t g_adj[NN * NWORDS];
__device__ uint32_t g_mask[NN * NWORDS];
__device__ __nv_bfloat16 g_xb[NN * DD];
__device__ __nv_bfloat16 g_Wb[4 * DD * DD];   // Wq, Wk, Wv, Wo (bf16)
__device__ __half g_Qh[NN * DD];              // fp16, pre-scaled by QSCALE
__device__ __half g_Kh[NN * DD];
__device__ __half g_Vh[NN * DD];
__device__ __nv_bfloat16 g_attb[NN * DD];     // attention output (bf16)
__device__ float g_pO[NSPLIT * NN * DD];      // split-KV partial O (unnormalized)
__device__ float g_pl[NSPLIT * HH * NN];      // split-KV partial row sums

// ---------------- PTX helpers ----------------
__device__ __forceinline__ uint32_t smem_u32(const void* p) {
    uint32_t a;
    asm("{ .reg .u64 t; cvta.to.shared.u64 t, %1; cvt.u32.u64 %0, t; }"
        : "=r"(a) : "l"(p));
    return a;
}
__device__ __forceinline__ uint32_t pack_bf16x2(float lo, float hi) {
    uint32_t r;
    asm("cvt.rn.bf16x2.f32 %0, %1, %2;" : "=r"(r) : "f"(hi), "f"(lo));
    return r;
}
__device__ __forceinline__ uint32_t pack_f16x2(float lo, float hi) {
    uint32_t r;
    asm("cvt.rn.f16x2.f32 %0, %1, %2;" : "=r"(r) : "f"(hi), "f"(lo));
    return r;
}
__device__ __forceinline__ uint32_t ex2_f16x2(uint32_t x) {
    uint32_t y;
    asm("ex2.approx.f16x2 %0, %1;" : "=r"(y) : "r"(x));
    return y;
}
__device__ __forceinline__ uint32_t hadd2(uint32_t a, uint32_t b) {
    uint32_t d;
    asm("add.rn.f16x2 %0, %1, %2;" : "=r"(d) : "r"(a), "r"(b));
    return d;
}
__device__ __forceinline__ uint32_t prmt(uint32_t a, uint32_t b, uint32_t sel) {
    uint32_t d;
    asm("prmt.b32 %0, %1, %2, %3;" : "=r"(d) : "r"(a), "r"(b), "r"(sel));
    return d;
}
__device__ __forceinline__ float2 h2_to_f2(uint32_t u) {
    __half2 h = *reinterpret_cast<__half2*>(&u);
    return __half22float2(h);
}
__device__ __forceinline__ void ldsm_x4(uint32_t* r, uint32_t addr) {
    asm volatile("ldmatrix.sync.aligned.m8n8.x4.shared.b16 {%0,%1,%2,%3}, [%4];"
        : "=r"(r[0]), "=r"(r[1]), "=r"(r[2]), "=r"(r[3]) : "r"(addr));
}
__device__ __forceinline__ void ldsm_x4_t(uint32_t* r, uint32_t addr) {
    asm volatile("ldmatrix.sync.aligned.m8n8.x4.trans.shared.b16 {%0,%1,%2,%3}, [%4];"
        : "=r"(r[0]), "=r"(r[1]), "=r"(r[2]), "=r"(r[3]) : "r"(addr));
}
__device__ __forceinline__ void mma_bf16(float* c, const uint32_t* a, const uint32_t* b) {
    asm volatile(
        "mma.sync.aligned.m16n8k16.row.col.f32.bf16.bf16.f32 "
        "{%0,%1,%2,%3}, {%4,%5,%6,%7}, {%8,%9}, {%0,%1,%2,%3};"
        : "+f"(c[0]), "+f"(c[1]), "+f"(c[2]), "+f"(c[3])
        : "r"(a[0]), "r"(a[1]), "r"(a[2]), "r"(a[3]), "r"(b[0]), "r"(b[1]));
}
// fp16 in, fp16 accumulate
__device__ __forceinline__ void mma_h(uint32_t* d, const uint32_t* a, const uint32_t* b) {
    asm volatile(
        "mma.sync.aligned.m16n8k16.row.col.f16.f16.f16.f16 "
        "{%0,%1}, {%2,%3,%4,%5}, {%6,%7}, {%0,%1};"
        : "+r"(d[0]), "+r"(d[1])
        : "r"(a[0]), "r"(a[1]), "r"(a[2]), "r"(a[3]), "r"(b[0]), "r"(b[1]));
}
__device__ __forceinline__ void cp16(uint32_t dst, const void* src) {
    asm volatile("cp.async.cg.shared.global [%0], [%1], 16;" :: "r"(dst), "l"(src));
}
#define CP_COMMIT() asm volatile("cp.async.commit_group;" ::: "memory")
#define CP_WAIT(n)  asm volatile("cp.async.wait_group %0;" :: "n"(n) : "memory")

// ================= K1: bf16 casts  ∥  adjacency init (one launch) =========
__global__ void __launch_bounds__(256) k1_kernel(const float* __restrict__ x,
                                                 const float* __restrict__ Wq,
                                                 const float* __restrict__ Wk,
                                                 const float* __restrict__ Wv,
                                                 const float* __restrict__ Wo) {
    int b = blockIdx.x;
    if (b < 1280) {
        int i = (b * 256 + threadIdx.x) * 4;
        const float* src;
        __nv_bfloat16* dst;
        if (i < NN * DD) {
            src = x + i; dst = g_xb + i;
        } else {
            int j = i - NN * DD;
            int w = j >> 16;
            int o = j & 65535;
            src = ((w == 0) ? Wq : (w == 1) ? Wk : (w == 2) ? Wv : Wo) + o;
            dst = g_Wb + w * (DD * DD) + o;
        }
        float4 v = *(const float4*)src;
        *(uint2*)dst = make_uint2(pack_bf16x2(v.x, v.y), pack_bf16x2(v.z, v.w));
    } else {
        int idx = (b - 1280) * 256 + threadIdx.x;
        int n = idx >> 7, w = idx & 127;
        uint32_t v = 0;
        if (w == (n >> 5)) v = 1u << (n & 31);
        g_adj[idx] = v;
    }
}

// ================= edge scatter (standalone) =================
__global__ void __launch_bounds__(128) edge_kernel(const int* __restrict__ ei) {
    int e = (blockIdx.x * 128 + threadIdx.x) * 4;   // 4 edges/thread
    uint4 s4 = *(const uint4*)(ei + e);
    uint4 d4 = *(const uint4*)(ei + EE + e);
    atomicOr(&g_adj[s4.x * NWORDS + (d4.x >> 5)], 1u << (d4.x & 31));
    atomicOr(&g_adj[d4.x * NWORDS + (s4.x >> 5)], 1u << (s4.x & 31));
    atomicOr(&g_adj[s4.y * NWORDS + (d4.y >> 5)], 1u << (d4.y & 31));
    atomicOr(&g_adj[d4.y * NWORDS + (s4.y >> 5)], 1u << (s4.y & 31));
    atomicOr(&g_adj[s4.z * NWORDS + (d4.z >> 5)], 1u << (d4.z & 31));
    atomicOr(&g_adj[d4.z * NWORDS + (s4.z >> 5)], 1u << (s4.z & 31));
    atomicOr(&g_adj[s4.w * NWORDS + (d4.w >> 5)], 1u << (d4.w & 31));
    atomicOr(&g_adj[d4.w * NWORDS + (s4.w >> 5)], 1u << (s4.w & 31));
}

// ================= bf16 tensor-core GEMM core (QKV; 64x128 tile) =========
__device__ __forceinline__ void gemm_core(const __nv_bfloat16* __restrict__ A,
                                          const __nv_bfloat16* __restrict__ W,
                                          const float* __restrict__ bias,
                                          __half* __restrict__ Cv, float scale) {
    __shared__ __nv_bfloat16 sA[2][64 * 40];
    __shared__ __nv_bfloat16 sB[2][32 * 136];

    const int tid = threadIdx.x;
    const int wid = tid >> 5;
    const int lane = tid & 31;
    const int m0 = blockIdx.y * 64;
    const int n0 = blockIdx.x * 128;

    const uint32_t aA = smem_u32(sA);
    const uint32_t aB = smem_u32(sB);
    const char* Abase = (const char*)A + (size_t)m0 * (DD * 2);
    const char* Bbase = (const char*)W + (size_t)n0 * 2;

    {
#pragma unroll
        for (int j = 0; j < 2; j++) {
            int t = tid + j * 128;
            int r = t >> 2, c = t & 3;
            cp16(aA + r * 80 + c * 16, Abase + (size_t)r * 512 + c * 16);
        }
#pragma unroll
        for (int j = 0; j < 4; j++) {
            int t = tid + j * 128;
            int r = t >> 4, c = t & 15;
            cp16(aB + r * 272 + c * 16, Bbase + (size_t)r * 512 + c * 16);
        }
        CP_COMMIT();
    }

    float acc[16][4];
#pragma unroll
    for (int j = 0; j < 16; j++)
        acc[j][0] = acc[j][1] = acc[j][2] = acc[j][3] = 0.f;

    const int m = lane >> 3, rr = lane & 7;
    const uint32_t a_off = (uint32_t)((wid * 16 + (m & 1) * 8 + rr) * 80 + (m >> 1) * 16);
    const uint32_t b_lane = (uint32_t)(((lane >> 3) & 1) * 8 * 272 + (lane & 7) * 272 +
                                       (lane >> 4) * 16);

    for (int t = 0; t < 8; t++) {
        if (t < 7) {
            int nb = (t + 1) & 1;
            uint32_t dA = aA + (uint32_t)nb * 5120;
            uint32_t dB = aB + (uint32_t)nb * 8704;
            const char* As = Abase + (size_t)(t + 1) * 64;
            const char* Bs = Bbase + (size_t)(t + 1) * 32 * 512;
#pragma unroll
            for (int j = 0; j < 2; j++) {
                int u = tid + j * 128;
                int r = u >> 2, c = u & 3;
                cp16(dA + r * 80 + c * 16, As + (size_t)r * 512 + c * 16);
            }
#pragma unroll
            for (int j = 0; j < 4; j++) {
                int u = tid + j * 128;
                int r = u >> 4, c = u & 15;
                cp16(dB + r * 272 + c * 16, Bs + (size_t)r * 512 + c * 16);
            }
            CP_COMMIT();
            CP_WAIT(1);
        } else {
            CP_WAIT(0);
        }
        __syncthreads();

        const uint32_t bufA = aA + (uint32_t)(t & 1) * 5120;
        const uint32_t bufB = aB + (uint32_t)(t & 1) * 8704;

        uint32_t aq[2][4];
        ldsm_x4(aq[0], bufA + a_off);
        ldsm_x4(aq[1], bufA + a_off + 32);

#pragma unroll
        for (int ks = 0; ks < 2; ks++) {
#pragma unroll
            for (int j = 0; j < 8; j++) {
                uint32_t vb[4];
                ldsm_x4_t(vb, bufB + (uint32_t)(ks * 16 * 272 + j * 32) + b_lane);
                mma_bf16(acc[2 * j],     aq[ks], vb);
                mma_bf16(acc[2 * j + 1], aq[ks], vb + 2);
            }
        }
        __syncthreads();
    }

    const int gg = lane >> 2, tig = lane & 3;
    const int r0 = m0 + wid * 16 + gg;
#pragma unroll
    for (int j = 0; j < 16; j++) {
        int col = n0 + j * 8 + 2 * tig;
        float2 b2 = __ldg((const float2*)(bias + col));
        *(uint32_t*)(Cv + (size_t)r0 * DD + col) =
            pack_f16x2((acc[j][0] + b2.x) * scale, (acc[j][1] + b2.y) * scale);
        *(uint32_t*)(Cv + (size_t)(r0 + 8) * DD + col) =
            pack_f16x2((acc[j][2] + b2.x) * scale, (acc[j][3] + b2.y) * scale);
    }
}

// ================= K3: QKV projections  ∥  reach-2 mask (one launch) ======
// grid (2, 64, 35): z=0..2 -> qkv gemm; z=3..34 -> mask nodes
__global__ void __launch_bounds__(128) k3_kernel(const float* __restrict__ bq,
                                                 const float* __restrict__ bk,
                                                 const float* __restrict__ bv) {
    int z = blockIdx.z;
    if (z < 3) {
        const float* bias = (z == 0) ? bq : (z == 1) ? bk : bv;
        __half* C = (z == 0) ? g_Qh : (z == 1) ? g_Kh : g_Vh;
        float scale = (z == 0) ? QSCALE : 1.f;
        gemm_core(g_xb, g_Wb + (size_t)z * DD * DD, bias, C, scale);
        return;
    }
    // ---- mask: one node per block, 128 threads ----
    int n = (z - 3) * 128 + blockIdx.y * 2 + blockIdx.x;
    int tid = threadIdx.x;
    int lane = tid & 31;
    __shared__ uint16_t nbr[1024];
    __shared__ int cnt;
    if (tid == 0) cnt = 0;
    __syncthreads();

    // phase 1: ballot-scan list build (1 atomic per warp)
    uint32_t bits = g_adj[n * NWORDS + tid];
    int pc = __popc(bits);
    int pref = pc;
#pragma unroll
    for (int o = 1; o < 32; o <<= 1) {
        int v = __shfl_up_sync(0xFFFFFFFFu, pref, o);
        if (lane >= o) pref += v;
    }
    int wtot = __shfl_sync(0xFFFFFFFFu, pref, 31);
    int wbase = 0;
    if (lane == 0) wbase = atomicAdd(&cnt, wtot);
    wbase = __shfl_sync(0xFFFFFFFFu, wbase, 0);
    int off = wbase + pref - pc;
    uint32_t bb = bits;
    while (bb) {
        int b = __ffs(bb) - 1;
        bb &= bb - 1;
        nbr[off++] = (uint16_t)((tid << 5) + b);
    }
    __syncthreads();

    // phase 2: OR neighbor rows, 8-deep MLP
    int c = cnt;
    uint32_t acc = 0;
    int i = 0;
    for (; i + 8 <= c; i += 8) {
        uint32_t a0 = g_adj[(int)nbr[i + 0] * NWORDS + tid];
        uint32_t a1 = g_adj[(int)nbr[i + 1] * NWORDS + tid];
        uint32_t a2 = g_adj[(int)nbr[i + 2] * NWORDS + tid];
        uint32_t a3 = g_adj[(int)nbr[i + 3] * NWORDS + tid];
        uint32_t a4 = g_adj[(int)nbr[i + 4] * NWORDS + tid];
        uint32_t a5 = g_adj[(int)nbr[i + 5] * NWORDS + tid];
        uint32_t a6 = g_adj[(int)nbr[i + 6] * NWORDS + tid];
        uint32_t a7 = g_adj[(int)nbr[i + 7] * NWORDS + tid];
        acc |= ((a0 | a1) | (a2 | a3)) | ((a4 | a5) | (a6 | a7));
    }
    for (; i < c; i++)
        acc |= g_adj[(int)nbr[i] * NWORDS + tid];
    g_mask[n * NWORDS + tid] = acc;
}

// ================= attention: split-KV x4, 4 CTAs/SM ======================
struct AttnSmemH {
    __half Qs[128 * 32];       // 8192 B (64B rows)
    __half Ks[2][128 * 40];    // 2 x 10240 B
    __half Vs[2][128 * 40];    // 2 x 10240 B
};                             // total 49152 B

__global__ void __launch_bounds__(256, 4) attn_kernel() {
    __shared__ AttnSmemH sm;
    const int tid = threadIdx.x;
    const int wid = tid >> 5;
    const int lane = tid & 31;
    const int h = blockIdx.y;
    const int q0 = blockIdx.x * 128;
    const int z = blockIdx.z;
    const int t0 = z * TILES_PER_SPLIT;
    const int t1 = t0 + TILES_PER_SPLIT;

    const uint32_t s_q = smem_u32(sm.Qs);
    const uint32_t s_k0 = smem_u32(sm.Ks[0]);
    const uint32_t s_v0 = smem_u32(sm.Vs[0]);

    const char* ksrc = (const char*)(g_Kh + h * HD);
    const char* vsrc = (const char*)(g_Vh + h * HD);

    // ---- prologue: Q + K(t0)/V(t0) via cp.async ----
    {
        const char* qsrc = (const char*)(g_Qh + (size_t)q0 * DD + h * HD);
        size_t tb = (size_t)t0 * 128 * 512;
#pragma unroll
        for (int j = 0; j < 2; j++) {
            int chunk = tid + j * 256;
            int r = chunk >> 2, c = chunk & 3;
            cp16(s_q + (uint32_t)(r * 64 + c * 16), qsrc + (size_t)r * 512 + c * 16);
        }
#pragma unroll
        for (int j = 0; j < 2; j++) {
            int chunk = tid + j * 256;
            int r = chunk >> 2, c = chunk & 3;
            uint32_t off = (uint32_t)(r * 80 + c * 16);
            size_t gs = tb + (size_t)r * 512 + c * 16;
            cp16(s_k0 + off, ksrc + gs);
            cp16(s_v0 + off, vsrc + gs);
        }
        CP_COMMIT();
    }

    const int wq0 = wid * 16;
    const int g = lane >> 2, tig = lane & 3;
    const int row0 = q0 + wq0 + g;
    const uint32_t* mrow_lo = g_mask + (size_t)row0 * NWORDS;
    const uint32_t* mrow_hi = g_mask + (size_t)(row0 + 8) * NWORDS;

    CP_WAIT(0);
    __syncthreads();

    uint32_t aq[2][4];
    {
        int m = lane >> 3, rr = lane & 7;
        uint32_t base = s_q + (uint32_t)((wq0 + (m & 1) * 8 + rr) * 64 + (m >> 1) * 16);
        ldsm_x4(aq[0], base);
        ldsm_x4(aq[1], base + 32);
    }

    uint32_t of[4][2];
#pragma unroll
    for (int v = 0; v < 4; v++) { of[v][0] = 0u; of[v][1] = 0u; }
    float ls0 = 0.f, ls1 = 0.f;

    const uint32_t k_lane_off = (uint32_t)((lane & 7) * 80 + (lane >> 3) * 16);
    const uint32_t v_lane_off = (uint32_t)(((lane >> 3) & 1) * 8 * 80 + (lane & 7) * 80 +
                                           (lane >> 4) * 16);

    for (int t = t0; t < t1; t++) {
        int buf = t & 1;
        if (t < t1 - 1) {
            int nb = (t + 1) & 1;
            uint32_t skb = s_k0 + (uint32_t)nb * 10240;
            uint32_t svb = s_v0 + (uint32_t)nb * 10240;
            size_t tb = (size_t)(t + 1) * 128 * 512;
#pragma unroll
            for (int j = 0; j < 2; j++) {
                int chunk = tid + j * 256;
                int r = chunk >> 2, c = chunk & 3;
                uint32_t off = (uint32_t)(r * 80 + c * 16);
                size_t gs = tb + (size_t)r * 512 + c * 16;
                cp16(skb + off, ksrc + gs);
                cp16(svb + off, vsrc + gs);
            }
            CP_COMMIT();
            CP_WAIT(1);
        } else {
            CP_WAIT(0);
        }
        uint4 mw_lo = __ldg((const uint4*)(mrow_lo + t * 4));
        uint4 mw_hi = __ldg((const uint4*)(mrow_hi + t * 4));
        __syncthreads();

        const uint32_t kb_base = s_k0 + (uint32_t)buf * 10240;
        const uint32_t vb_base = s_v0 + (uint32_t)buf * 10240;
        const uint32_t mwl[4] = {mw_lo.x, mw_lo.y, mw_lo.z, mw_lo.w};
        const uint32_t mwh[4] = {mw_hi.x, mw_hi.y, mw_hi.z, mw_hi.w};

        uint32_t acc01 = 0, acc23 = 0;
#pragma unroll
        for (int qd = 0; qd < 4; qd++) {
            uint32_t kb[4][4];
#pragma unroll
            for (int nt = 0; nt < 4; nt++)
                ldsm_x4(kb[nt], kb_base + (uint32_t)((qd * 4 + nt) * (8 * 80)) + k_lane_off);
            uint32_t w0 = mwl[qd] >> (2 * tig);
            uint32_t w1 = mwh[qd] >> (2 * tig);
            uint32_t y1 = (w0 & 0x01010101u) << 7;
            uint32_t y2 = (w0 & 0x02020202u) << 6;
            uint32_t z1 = (w1 & 0x01010101u) << 7;
            uint32_t z2 = (w1 & 0x02020202u) << 6;
            uint32_t ap[2][4];
#pragma unroll
            for (int nt = 0; nt < 4; nt++) {
                uint32_t sd[2] = {0u, 0u};
                mma_h(sd, aq[0], kb[nt]);
                mma_h(sd, aq[1], kb[nt] + 2);
                uint32_t sel = 0xCC88u + (uint32_t)nt * 0x1111u;
                uint32_t p01 = ex2_f16x2(sd[0]) & prmt(y1, y2, sel);
                uint32_t p23 = ex2_f16x2(sd[1]) & prmt(z1, z2, sel);
                acc01 = hadd2(acc01, p01);
                acc23 = hadd2(acc23, p23);
                ap[nt >> 1][(nt & 1) * 2 + 0] = p01;
                ap[nt >> 1][(nt & 1) * 2 + 1] = p23;
            }
#pragma unroll
            for (int j = 0; j < 2; j++) {
                int kt = qd * 2 + j;
                uint32_t vb[4];
                uint32_t base = vb_base + (uint32_t)kt * (16 * 80) + v_lane_off;
                ldsm_x4_t(vb, base);
                mma_h(of[0], ap[j], vb);
                mma_h(of[1], ap[j], vb + 2);
                ldsm_x4_t(vb, base + 32);
                mma_h(of[2], ap[j], vb);
                mma_h(of[3], ap[j], vb + 2);
            }
        }
        {
            float2 f0 = h2_to_f2(acc01);
            float2 f1 = h2_to_f2(acc23);
            ls0 += f0.x + f0.y;
            ls1 += f1.x + f1.y;
        }
        __syncthreads();
    }

    ls0 += __shfl_xor_sync(0xFFFFFFFFu, ls0, 1);
    ls0 += __shfl_xor_sync(0xFFFFFFFFu, ls0, 2);
    ls1 += __shfl_xor_sync(0xFFFFFFFFu, ls1, 1);
    ls1 += __shfl_xor_sync(0xFFFFFFFFu, ls1, 2);

    float* p0 = g_pO + (size_t)z * NN * DD + (size_t)row0 * DD + h * HD + 2 * tig;
    float* p1 = p0 + 8 * DD;
#pragma unroll
    for (int v = 0; v < 4; v++) {
        *(float2*)(p0 + v * 8) = h2_to_f2(of[v][0]);
        *(float2*)(p1 + v * 8) = h2_to_f2(of[v][1]);
    }
    if (tig == 0) {
        g_pl[z * HH * NN + h * NN + row0] = ls0;
        g_pl[z * HH * NN + h * NN + row0 + 8] = ls1;
    }
}

// ================= combine split-KV partials -> bf16 attended =============
__global__ void __launch_bounds__(256) combine_kernel() {
    int i = (blockIdx.x * 256 + threadIdx.x) * 4;   // over NN*DD
    int n = i >> 8;            // DD = 256
    int c = i & 255;
    int h = c >> 5;
    float l = 0.f;
#pragma unroll
    for (int zz = 0; zz < NSPLIT; zz++)
        l += g_pl[zz * HH * NN + h * NN + n];
    float inv = 1.f / l;
    float4 a = *(const float4*)(g_pO + i);
#pragma unroll
    for (int zz = 1; zz < NSPLIT; zz++) {
        float4 b = *(const float4*)(g_pO + (size_t)zz * NN * DD + i);
        a.x += b.x; a.y += b.y; a.z += b.z; a.w += b.w;
    }
    *(uint2*)(g_attb + i) = make_uint2(
        pack_bf16x2(a.x * inv, a.y * inv),
        pack_bf16x2(a.z * inv, a.w * inv));
}

// ================= fused Wo GEMM + residual + LayerNorm ====================
__global__ void __launch_bounds__(256) wo_ln_kernel(const float* __restrict__ bo,
                                                    const float* __restrict__ x,
                                                    const float* __restrict__ lnw,
                                                    const float* __restrict__ lnb,
                                                    float* __restrict__ out) {
    __shared__ __nv_bfloat16 sA[2][64 * 40];     // 2 x 5120 B
    __shared__ __nv_bfloat16 sB[2][32 * 264];    // 2 x 16896 B (528B rows)
    __shared__ float sW[256], sBb[256];
    __shared__ float s1buf[2][64], s2buf[2][64];

    const int tid = threadIdx.x;
    const int wid = tid >> 5;
    const int lane = tid & 31;
    const int m0 = blockIdx.x * 64;
    const int rgrp = wid & 3;
    const int cgrp = wid >> 2;

    const uint32_t aA = smem_u32(sA);
    const uint32_t aB = smem_u32(sB);
    const char* Abase = (const char*)g_attb + (size_t)m0 * (DD * 2);
    const char* Bbase = (const char*)(g_Wb + (size_t)3 * DD * DD);

    sW[tid] = lnw[tid];
    sBb[tid] = lnb[tid];

    {
        int r = tid >> 2, c = tid & 3;
        cp16(aA + r * 80 + c * 16, Abase + (size_t)r * 512 + c * 16);
#pragma unroll
        for (int j = 0; j < 4; j++) {
            int u = tid + j * 256;
            int br = u >> 5, bc = u & 31;
            cp16(aB + br * 528 + bc * 16, Bbase + (size_t)br * 512 + bc * 16);
        }
        CP_COMMIT();
    }

    float acc[16][4];
#pragma unroll
    for (int j = 0; j < 16; j++)
        acc[j][0] = acc[j][1] = acc[j][2] = acc[j][3] = 0.f;

    const int m = lane >> 3, rr = lane & 7;
    const uint32_t a_off = (uint32_t)((rgrp * 16 + (m & 1) * 8 + rr) * 80 + (m >> 1) * 16);
    const uint32_t b_lane = (uint32_t)(((lane >> 3) & 1) * 8 * 528 + (lane & 7) * 528 +
                                       (lane >> 4) * 16);

    for (int t = 0; t < 8; t++) {
        if (t < 7) {
            int nb = (t + 1) & 1;
            uint32_t dA = aA + (uint32_t)nb * 5120;
            uint32_t dB = aB + (uint32_t)nb * 16896;
            const char* As = Abase + (size_t)(t + 1) * 64;
            const char* Bs = Bbase + (size_t)(t + 1) * 32 * 512;
            {
                int r = tid >> 2, c = tid & 3;
                cp16(dA + r * 80 + c * 16, As + (size_t)r * 512 + c * 16);
            }
#pragma unroll
            for (int j = 0; j < 4; j++) {
                int u = tid + j * 256;
                int br = u >> 5, bc = u & 31;
                cp16(dB + br * 528 + bc * 16, Bs + (size_t)br * 512 + bc * 16);
            }
            CP_COMMIT();
            CP_WAIT(1);
        } else {
            CP_WAIT(0);
        }
        __syncthreads();

        const uint32_t bufA = aA + (uint32_t)(t & 1) * 5120;
        const uint32_t bufB = aB + (uint32_t)(t & 1) * 16896;

        uint32_t aq[2][4];
        ldsm_x4(aq[0], bufA + a_off);
        ldsm_x4(aq[1], bufA + a_off + 32);

#pragma unroll
        for (int ks = 0; ks < 2; ks++) {
#pragma unroll
            for (int j = 0; j < 8; j++) {
                uint32_t vb[4];
                ldsm_x4_t(vb, bufB + (uint32_t)(ks * 16 * 528 + cgrp * 256 + j * 32) + b_lane);
                mma_bf16(acc[2 * j],     aq[ks], vb);
                mma_bf16(acc[2 * j + 1], aq[ks], vb + 2);
            }
        }
        __syncthreads();
    }

    const int g = lane >> 2, tig = lane & 3;
    const int rloc0 = rgrp * 16 + g;
    const int rloc1 = rloc0 + 8;
    const int r0 = m0 + rloc0;
    float s1a = 0.f, s2a = 0.f, s1b = 0.f, s2b = 0.f;
#pragma unroll
    for (int j = 0; j < 16; j++) {
        int col = cgrp * 128 + j * 8 + 2 * tig;
        float2 b2 = __ldg((const float2*)(bo + col));
        float2 xa = __ldg((const float2*)(x + (size_t)r0 * DD + col));
        float2 xb = __ldg((const float2*)(x + (size_t)(r0 + 8) * DD + col));
        float v0 = acc[j][0] + b2.x + xa.x;
        float v1 = acc[j][1] + b2.y + xa.y;
        float v2 = acc[j][2] + b2.x + xb.x;
        float v3 = acc[j][3] + b2.y + xb.y;
        acc[j][0] = v0; acc[j][1] = v1; acc[j][2] = v2; acc[j][3] = v3;
        s1a += v0 + v1; s2a += v0 * v0 + v1 * v1;
        s1b += v2 + v3; s2b += v2 * v2 + v3 * v3;
    }
    s1a += __shfl_xor_sync(0xFFFFFFFFu, s1a, 1);
    s1a += __shfl_xor_sync(0xFFFFFFFFu, s1a, 2);
    s2a += __shfl_xor_sync(0xFFFFFFFFu, s2a, 1);
    s2a += __shfl_xor_sync(0xFFFFFFFFu, s2a, 2);
    s1b += __shfl_xor_sync(0xFFFFFFFFu, s1b, 1);
    s1b += __shfl_xor_sync(0xFFFFFFFFu, s1b, 2);
    s2b += __shfl_xor_sync(0xFFFFFFFFu, s2b, 1);
    s2b += __shfl_xor_sync(0xFFFFFFFFu, s2b, 2);
    if (tig == 0) {
        s1buf[cgrp][rloc0] = s1a; s2buf[cgrp][rloc0] = s2a;
        s1buf[cgrp][rloc1] = s1b; s2buf[cgrp][rloc1] = s2b;
    }
    __syncthreads();
    float mu0 = (s1buf[0][rloc0] + s1buf[1][rloc0]) * (1.f / 256.f);
    float va0 = (s2buf[0][rloc0] + s2buf[1][rloc0]) * (1.f / 256.f) - mu0 * mu0;
    float inv0 = rsqrtf(va0 + 1e-5f);
    float mu1 = (s1buf[0][rloc1] + s1buf[1][rloc1]) * (1.f / 256.f);
    float va1 = (s2buf[0][rloc1] + s2buf[1][rloc1]) * (1.f / 256.f) - mu1 * mu1;
    float inv1 = rsqrtf(va1 + 1e-5f);
#pragma unroll
    for (int j = 0; j < 16; j++) {
        int col = cgrp * 128 + j * 8 + 2 * tig;
        float w0 = sW[col], w1 = sW[col + 1];
        float c0 = sBb[col], c1 = sBb[col + 1];
        *(float2*)(out + (size_t)r0 * DD + col) =
            make_float2((acc[j][0] - mu0) * inv0 * w0 + c0,
                        (acc[j][1] - mu0) * inv0 * w1 + c1);
        *(float2*)(out + (size_t)(r0 + 8) * DD + col) =
            make_float2((acc[j][2] - mu1) * inv1 * w0 + c0,
                        (acc[j][3] - mu1) * inv1 * w1 + c1);
    }
}

// ================= launch =================
extern "C" void kernel_launch(void* const* d_in, const int* in_sizes, int n_in,
                              void* d_out, int out_size) {
    const float* x   = (const float*)d_in[0];
    const int*   ei  = (const int*)d_in[1];
    const float* Wq  = (const float*)d_in[2];
    const float* bq  = (const float*)d_in[3];
    const float* Wk  = (const float*)d_in[4];
    const float* bk  = (const float*)d_in[5];
    const float* Wv  = (const float*)d_in[6];
    const float* bv  = (const float*)d_in[7];
    const float* Wo  = (const float*)d_in[8];
    const float* bo  = (const float*)d_in[9];
    const float* lnw = (const float*)d_in[10];
    const float* lnb = (const float*)d_in[11];
    float* out = (float*)d_out;

    // K1: casts ∥ adjacency init
    k1_kernel<<<3328, 256>>>(x, Wq, Wk, Wv, Wo);
    // edge scatter
    edge_kernel<<<EE / 512, 128>>>(ei);
    // K3: QKV projections ∥ reach-2 mask
    k3_kernel<<<dim3(2, 64, 35), 128>>>(bq, bk, bv);
    // tensor-core attention, split-KV 4-way, 4 CTAs/SM
    attn_kernel<<<dim3(NN / 128, HH, NSPLIT), 256>>>();
    // combine partials
    combine_kernel<<<NN * DD / 1024, 256>>>();
    // fused Wo GEMM + residual + LayerNorm
    wo_ln_kernel<<<NN / 64, 256>>>(bo, x, lnw, lnb, out);
}

// round 16
// speedup vs baseline: 1.1026x; 1.0230x over previous
#include <cuda_runtime.h>
#include <cuda_bf16.h>
#include <cuda_fp16.h>
#include <math.h>
#include <stdint.h>

// ---------------- problem constants ----------------
#define NN 4096
#define DD 256
#define HH 8
#define HD 32
#define EE 65536
#define NWORDS 128
// (1/sqrt(32)) * log2(e): folded into Q so softmax weight = exp2(S)
#define QSCALE 0.25503486f
#define NSPLIT 4
#define TILES_PER_SPLIT 8

// ---------------- scratch globals (no allocs allowed) ----------------
__device__ uint32_t g_adj[NN * NWORDS];
__device__ uint32_t g_mask[NN * NWORDS];
__device__ __nv_bfloat16 g_xb[NN * DD];
__device__ __nv_bfloat16 g_Wb[4 * DD * DD];   // Wq, Wk, Wv, Wo (bf16)
__device__ __half g_Qh[NN * DD];              // fp16, pre-scaled by QSCALE
__device__ __half g_Kh[NN * DD];
__device__ __half g_Vh[NN * DD];
__device__ __nv_bfloat16 g_attb[NN * DD];     // attention output (bf16)
__device__ uint32_t g_pOh[NSPLIT * NN * DD / 2]; // split-KV partial O (f16x2)
__device__ float g_pl[NSPLIT * HH * NN];      // split-KV partial row sums

// ---------------- PTX helpers ----------------
__device__ __forceinline__ uint32_t smem_u32(const void* p) {
    uint32_t a;
    asm("{ .reg .u64 t; cvta.to.shared.u64 t, %1; cvt.u32.u64 %0, t; }"
        : "=r"(a) : "l"(p));
    return a;
}
__device__ __forceinline__ uint32_t pack_bf16x2(float lo, float hi) {
    uint32_t r;
    asm("cvt.rn.bf16x2.f32 %0, %1, %2;" : "=r"(r) : "f"(hi), "f"(lo));
    return r;
}
__device__ __forceinline__ uint32_t pack_f16x2(float lo, float hi) {
    uint32_t r;
    asm("cvt.rn.f16x2.f32 %0, %1, %2;" : "=r"(r) : "f"(hi), "f"(lo));
    return r;
}
__device__ __forceinline__ uint32_t ex2_f16x2(uint32_t x) {
    uint32_t y;
    asm("ex2.approx.f16x2 %0, %1;" : "=r"(y) : "r"(x));
    return y;
}
__device__ __forceinline__ uint32_t hadd2(uint32_t a, uint32_t b) {
    uint32_t d;
    asm("add.rn.f16x2 %0, %1, %2;" : "=r"(d) : "r"(a), "r"(b));
    return d;
}
__device__ __forceinline__ uint32_t prmt(uint32_t a, uint32_t b, uint32_t sel) {
    uint32_t d;
    asm("prmt.b32 %0, %1, %2, %3;" : "=r"(d) : "r"(a), "r"(b), "r"(sel));
    return d;
}
__device__ __forceinline__ float2 h2_to_f2(uint32_t u) {
    __half2 h = *reinterpret_cast<__half2*>(&u);
    return __half22float2(h);
}
__device__ __forceinline__ void ldsm_x4(uint32_t* r, uint32_t addr) {
    asm volatile("ldmatrix.sync.aligned.m8n8.x4.shared.b16 {%0,%1,%2,%3}, [%4];"
        : "=r"(r[0]), "=r"(r[1]), "=r"(r[2]), "=r"(r[3]) : "r"(addr));
}
__device__ __forceinline__ void ldsm_x4_t(uint32_t* r, uint32_t addr) {
    asm volatile("ldmatrix.sync.aligned.m8n8.x4.trans.shared.b16 {%0,%1,%2,%3}, [%4];"
        : "=r"(r[0]), "=r"(r[1]), "=r"(r[2]), "=r"(r[3]) : "r"(addr));
}
__device__ __forceinline__ void mma_bf16(float* c, const uint32_t* a, const uint32_t* b) {
    asm volatile(
        "mma.sync.aligned.m16n8k16.row.col.f32.bf16.bf16.f32 "
        "{%0,%1,%2,%3}, {%4,%5,%6,%7}, {%8,%9}, {%0,%1,%2,%3};"
        : "+f"(c[0]), "+f"(c[1]), "+f"(c[2]), "+f"(c[3])
        : "r"(a[0]), "r"(a[1]), "r"(a[2]), "r"(a[3]), "r"(b[0]), "r"(b[1]));
}
// fp16 in, fp16 accumulate
__device__ __forceinline__ void mma_h(uint32_t* d, const uint32_t* a, const uint32_t* b) {
    asm volatile(
        "mma.sync.aligned.m16n8k16.row.col.f16.f16.f16.f16 "
        "{%0,%1}, {%2,%3,%4,%5}, {%6,%7}, {%0,%1};"
        : "+r"(d[0]), "+r"(d[1])
        : "r"(a[0]), "r"(a[1]), "r"(a[2]), "r"(a[3]), "r"(b[0]), "r"(b[1]));
}
__device__ __forceinline__ void cp16(uint32_t dst, const void* src) {
    asm volatile("cp.async.cg.shared.global [%0], [%1], 16;" :: "r"(dst), "l"(src));
}
#define CP_COMMIT() asm volatile("cp.async.commit_group;" ::: "memory")
#define CP_WAIT(n)  asm volatile("cp.async.wait_group %0;" :: "n"(n) : "memory")

// ================= K1: bf16 casts  ∥  adjacency init (one launch) =========
__global__ void __launch_bounds__(256) k1_kernel(const float* __restrict__ x,
                                                 const float* __restrict__ Wq,
                                                 const float* __restrict__ Wk,
                                                 const float* __restrict__ Wv,
                                                 const float* __restrict__ Wo) {
    int b = blockIdx.x;
    if (b < 1280) {
        int i = (b * 256 + threadIdx.x) * 4;
        const float* src;
        __nv_bfloat16* dst;
        if (i < NN * DD) {
            src = x + i; dst = g_xb + i;
        } else {
            int j = i - NN * DD;
            int w = j >> 16;
            int o = j & 65535;
            src = ((w == 0) ? Wq : (w == 1) ? Wk : (w == 2) ? Wv : Wo) + o;
            dst = g_Wb + w * (DD * DD) + o;
        }
        float4 v = *(const float4*)src;
        *(uint2*)dst = make_uint2(pack_bf16x2(v.x, v.y), pack_bf16x2(v.z, v.w));
    } else {
        int idx = (b - 1280) * 256 + threadIdx.x;
        int n = idx >> 7, w = idx & 127;
        uint32_t v = 0;
        if (w == (n >> 5)) v = 1u << (n & 31);
        g_adj[idx] = v;
    }
}

// ================= edge scatter (standalone) =================
__global__ void __launch_bounds__(128) edge_kernel(const int* __restrict__ ei) {
    int e = (blockIdx.x * 128 + threadIdx.x) * 4;   // 4 edges/thread
    uint4 s4 = *(const uint4*)(ei + e);
    uint4 d4 = *(const uint4*)(ei + EE + e);
    atomicOr(&g_adj[s4.x * NWORDS + (d4.x >> 5)], 1u << (d4.x & 31));
    atomicOr(&g_adj[d4.x * NWORDS + (s4.x >> 5)], 1u << (s4.x & 31));
    atomicOr(&g_adj[s4.y * NWORDS + (d4.y >> 5)], 1u << (d4.y & 31));
    atomicOr(&g_adj[d4.y * NWORDS + (s4.y >> 5)], 1u << (s4.y & 31));
    atomicOr(&g_adj[s4.z * NWORDS + (d4.z >> 5)], 1u << (d4.z & 31));
    atomicOr(&g_adj[d4.z * NWORDS + (s4.z >> 5)], 1u << (s4.z & 31));
    atomicOr(&g_adj[s4.w * NWORDS + (d4.w >> 5)], 1u << (d4.w & 31));
    atomicOr(&g_adj[d4.w * NWORDS + (s4.w >> 5)], 1u << (s4.w & 31));
}

// ================= bf16 tensor-core GEMM core (QKV; 64x128 tile) =========
__device__ __forceinline__ void gemm_core(const __nv_bfloat16* __restrict__ A,
                                          const __nv_bfloat16* __restrict__ W,
                                          const float* __restrict__ bias,
                                          __half* __restrict__ Cv, float scale) {
    __shared__ __nv_bfloat16 sA[2][64 * 40];
    __shared__ __nv_bfloat16 sB[2][32 * 136];

    const int tid = threadIdx.x;
    const int wid = tid >> 5;
    const int lane = tid & 31;
    const int m0 = blockIdx.y * 64;
    const int n0 = blockIdx.x * 128;

    const uint32_t aA = smem_u32(sA);
    const uint32_t aB = smem_u32(sB);
    const char* Abase = (const char*)A + (size_t)m0 * (DD * 2);
    const char* Bbase = (const char*)W + (size_t)n0 * 2;

    {
#pragma unroll
        for (int j = 0; j < 2; j++) {
            int t = tid + j * 128;
            int r = t >> 2, c = t & 3;
            cp16(aA + r * 80 + c * 16, Abase + (size_t)r * 512 + c * 16);
        }
#pragma unroll
        for (int j = 0; j < 4; j++) {
            int t = tid + j * 128;
            int r = t >> 4, c = t & 15;
            cp16(aB + r * 272 + c * 16, Bbase + (size_t)r * 512 + c * 16);
        }
        CP_COMMIT();
    }

    float acc[16][4];
#pragma unroll
    for (int j = 0; j < 16; j++)
        acc[j][0] = acc[j][1] = acc[j][2] = acc[j][3] = 0.f;

    const int m = lane >> 3, rr = lane & 7;
    const uint32_t a_off = (uint32_t)((wid * 16 + (m & 1) * 8 + rr) * 80 + (m >> 1) * 16);
    const uint32_t b_lane = (uint32_t)(((lane >> 3) & 1) * 8 * 272 + (lane & 7) * 272 +
                                       (lane >> 4) * 16);

    for (int t = 0; t < 8; t++) {
        if (t < 7) {
            int nb = (t + 1) & 1;
            uint32_t dA = aA + (uint32_t)nb * 5120;
            uint32_t dB = aB + (uint32_t)nb * 8704;
            const char* As = Abase + (size_t)(t + 1) * 64;
            const char* Bs = Bbase + (size_t)(t + 1) * 32 * 512;
#pragma unroll
            for (int j = 0; j < 2; j++) {
                int u = tid + j * 128;
                int r = u >> 2, c = u & 3;
                cp16(dA + r * 80 + c * 16, As + (size_t)r * 512 + c * 16);
            }
#pragma unroll
            for (int j = 0; j < 4; j++) {
                int u = tid + j * 128;
                int r = u >> 4, c = u & 15;
                cp16(dB + r * 272 + c * 16, Bs + (size_t)r * 512 + c * 16);
            }
            CP_COMMIT();
            CP_WAIT(1);
        } else {
            CP_WAIT(0);
        }
        __syncthreads();

        const uint32_t bufA = aA + (uint32_t)(t & 1) * 5120;
        const uint32_t bufB = aB + (uint32_t)(t & 1) * 8704;

        uint32_t aq[2][4];
        ldsm_x4(aq[0], bufA + a_off);
        ldsm_x4(aq[1], bufA + a_off + 32);

#pragma unroll
        for (int ks = 0; ks < 2; ks++) {
#pragma unroll
            for (int j = 0; j < 8; j++) {
                uint32_t vb[4];
                ldsm_x4_t(vb, bufB + (uint32_t)(ks * 16 * 272 + j * 32) + b_lane);
                mma_bf16(acc[2 * j],     aq[ks], vb);
                mma_bf16(acc[2 * j + 1], aq[ks], vb + 2);
            }
        }
        __syncthreads();
    }

    const int gg = lane >> 2, tig = lane & 3;
    const int r0 = m0 + wid * 16 + gg;
#pragma unroll
    for (int j = 0; j < 16; j++) {
        int col = n0 + j * 8 + 2 * tig;
        float2 b2 = __ldg((const float2*)(bias + col));
        *(uint32_t*)(Cv + (size_t)r0 * DD + col) =
            pack_f16x2((acc[j][0] + b2.x) * scale, (acc[j][1] + b2.y) * scale);
        *(uint32_t*)(Cv + (size_t)(r0 + 8) * DD + col) =
            pack_f16x2((acc[j][2] + b2.x) * scale, (acc[j][3] + b2.y) * scale);
    }
}

// ================= K3: QKV projections  ∥  reach-2 mask (one launch) ======
// grid (2, 64, 35): z=0..2 -> qkv gemm; z=3..34 -> mask nodes
__global__ void __launch_bounds__(128) k3_kernel(const float* __restrict__ bq,
                                                 const float* __restrict__ bk,
                                                 const float* __restrict__ bv) {
    int z = blockIdx.z;
    if (z < 3) {
        const float* bias = (z == 0) ? bq : (z == 1) ? bk : bv;
        __half* C = (z == 0) ? g_Qh : (z == 1) ? g_Kh : g_Vh;
        float scale = (z == 0) ? QSCALE : 1.f;
        gemm_core(g_xb, g_Wb + (size_t)z * DD * DD, bias, C, scale);
        return;
    }
    // ---- mask: one node per block, 128 threads ----
    int n = (z - 3) * 128 + blockIdx.y * 2 + blockIdx.x;
    int tid = threadIdx.x;
    int lane = tid & 31;
    __shared__ uint16_t nbr[1024];
    __shared__ int cnt;
    if (tid == 0) cnt = 0;
    __syncthreads();

    // phase 1: ballot-scan list build (1 atomic per warp)
    uint32_t bits = g_adj[n * NWORDS + tid];
    int pc = __popc(bits);
    int pref = pc;
#pragma unroll
    for (int o = 1; o < 32; o <<= 1) {
        int v = __shfl_up_sync(0xFFFFFFFFu, pref, o);
        if (lane >= o) pref += v;
    }
    int wtot = __shfl_sync(0xFFFFFFFFu, pref, 31);
    int wbase = 0;
    if (lane == 0) wbase = atomicAdd(&cnt, wtot);
    wbase = __shfl_sync(0xFFFFFFFFu, wbase, 0);
    int off = wbase + pref - pc;
    uint32_t bb = bits;
    while (bb) {
        int b = __ffs(bb) - 1;
        bb &= bb - 1;
        nbr[off++] = (uint16_t)((tid << 5) + b);
    }
    __syncthreads();

    // phase 2: OR neighbor rows, 8-deep MLP
    int c = cnt;
    uint32_t acc = 0;
    int i = 0;
    for (; i + 8 <= c; i += 8) {
        uint32_t a0 = g_adj[(int)nbr[i + 0] * NWORDS + tid];
        uint32_t a1 = g_adj[(int)nbr[i + 1] * NWORDS + tid];
        uint32_t a2 = g_adj[(int)nbr[i + 2] * NWORDS + tid];
        uint32_t a3 = g_adj[(int)nbr[i + 3] * NWORDS + tid];
        uint32_t a4 = g_adj[(int)nbr[i + 4] * NWORDS + tid];
        uint32_t a5 = g_adj[(int)nbr[i + 5] * NWORDS + tid];
        uint32_t a6 = g_adj[(int)nbr[i + 6] * NWORDS + tid];
        uint32_t a7 = g_adj[(int)nbr[i + 7] * NWORDS + tid];
        acc |= ((a0 | a1) | (a2 | a3)) | ((a4 | a5) | (a6 | a7));
    }
    for (; i < c; i++)
        acc |= g_adj[(int)nbr[i] * NWORDS + tid];
    g_mask[n * NWORDS + tid] = acc;
}

// ================= attention: split-KV x4, 4 CTAs/SM ======================
struct AttnSmemH {
    __half Qs[128 * 32];       // 8192 B (64B rows)
    __half Ks[2][128 * 40];    // 2 x 10240 B
    __half Vs[2][128 * 40];    // 2 x 10240 B
};                             // total 49152 B

__global__ void __launch_bounds__(256, 4) attn_kernel() {
    __shared__ AttnSmemH sm;
    const int tid = threadIdx.x;
    const int wid = tid >> 5;
    const int lane = tid & 31;
    const int h = blockIdx.y;
    const int q0 = blockIdx.x * 128;
    const int z = blockIdx.z;
    const int t0 = z * TILES_PER_SPLIT;
    const int t1 = t0 + TILES_PER_SPLIT;

    const uint32_t s_q = smem_u32(sm.Qs);
    const uint32_t s_k0 = smem_u32(sm.Ks[0]);
    const uint32_t s_v0 = smem_u32(sm.Vs[0]);

    const char* ksrc = (const char*)(g_Kh + h * HD);
    const char* vsrc = (const char*)(g_Vh + h * HD);

    // ---- prologue: Q + K(t0)/V(t0) via cp.async ----
    {
        const char* qsrc = (const char*)(g_Qh + (size_t)q0 * DD + h * HD);
        size_t tb = (size_t)t0 * 128 * 512;
#pragma unroll
        for (int j = 0; j < 2; j++) {
            int chunk = tid + j * 256;
            int r = chunk >> 2, c = chunk & 3;
            cp16(s_q + (uint32_t)(r * 64 + c * 16), qsrc + (size_t)r * 512 + c * 16);
        }
#pragma unroll
        for (int j = 0; j < 2; j++) {
            int chunk = tid + j * 256;
            int r = chunk >> 2, c = chunk & 3;
            uint32_t off = (uint32_t)(r * 80 + c * 16);
            size_t gs = tb + (size_t)r * 512 + c * 16;
            cp16(s_k0 + off, ksrc + gs);
            cp16(s_v0 + off, vsrc + gs);
        }
        CP_COMMIT();
    }

    const int wq0 = wid * 16;
    const int g = lane >> 2, tig = lane & 3;
    const int row0 = q0 + wq0 + g;
    const uint32_t* mrow_lo = g_mask + (size_t)row0 * NWORDS;
    const uint32_t* mrow_hi = g_mask + (size_t)(row0 + 8) * NWORDS;

    CP_WAIT(0);
    __syncthreads();

    uint32_t aq[2][4];
    {
        int m = lane >> 3, rr = lane & 7;
        uint32_t base = s_q + (uint32_t)((wq0 + (m & 1) * 8 + rr) * 64 + (m >> 1) * 16);
        ldsm_x4(aq[0], base);
        ldsm_x4(aq[1], base + 32);
    }

    uint32_t of[4][2];
#pragma unroll
    for (int v = 0; v < 4; v++) { of[v][0] = 0u; of[v][1] = 0u; }
    float ls0 = 0.f, ls1 = 0.f;

    const uint32_t k_lane_off = (uint32_t)((lane & 7) * 80 + (lane >> 3) * 16);
    const uint32_t v_lane_off = (uint32_t)(((lane >> 3) & 1) * 8 * 80 + (lane & 7) * 80 +
                                           (lane >> 4) * 16);

    for (int t = t0; t < t1; t++) {
        int buf = t & 1;
        // issue this tile's mask loads first (independent of cp.async groups)
        uint4 mw_lo = __ldg((const uint4*)(mrow_lo + t * 4));
        uint4 mw_hi = __ldg((const uint4*)(mrow_hi + t * 4));
        if (t < t1 - 1) {
            int nb = (t + 1) & 1;
            uint32_t skb = s_k0 + (uint32_t)nb * 10240;
            uint32_t svb = s_v0 + (uint32_t)nb * 10240;
            size_t tb = (size_t)(t + 1) * 128 * 512;
#pragma unroll
            for (int j = 0; j < 2; j++) {
                int chunk = tid + j * 256;
                int r = chunk >> 2, c = chunk & 3;
                uint32_t off = (uint32_t)(r * 80 + c * 16);
                size_t gs = tb + (size_t)r * 512 + c * 16;
                cp16(skb + off, ksrc + gs);
                cp16(svb + off, vsrc + gs);
            }
            CP_COMMIT();
            CP_WAIT(1);
        } else {
            CP_WAIT(0);
        }
        __syncthreads();

        const uint32_t kb_base = s_k0 + (uint32_t)buf * 10240;
        const uint32_t vb_base = s_v0 + (uint32_t)buf * 10240;
        const uint32_t mwl[4] = {mw_lo.x, mw_lo.y, mw_lo.z, mw_lo.w};
        const uint32_t mwh[4] = {mw_hi.x, mw_hi.y, mw_hi.z, mw_hi.w};

        uint32_t acc01 = 0, acc23 = 0;
#pragma unroll
        for (int qd = 0; qd < 4; qd++) {
            uint32_t kb[4][4];
#pragma unroll
            for (int nt = 0; nt < 4; nt++)
                ldsm_x4(kb[nt], kb_base + (uint32_t)((qd * 4 + nt) * (8 * 80)) + k_lane_off);
            uint32_t w0 = mwl[qd] >> (2 * tig);
            uint32_t w1 = mwh[qd] >> (2 * tig);
            uint32_t y1 = (w0 & 0x01010101u) << 7;
            uint32_t y2 = (w0 & 0x02020202u) << 6;
            uint32_t z1 = (w1 & 0x01010101u) << 7;
            uint32_t z2 = (w1 & 0x02020202u) << 6;
            uint32_t ap[2][4];
#pragma unroll
            for (int nt = 0; nt < 4; nt++) {
                uint32_t sd[2] = {0u, 0u};
                mma_h(sd, aq[0], kb[nt]);
                mma_h(sd, aq[1], kb[nt] + 2);
                uint32_t sel = 0xCC88u + (uint32_t)nt * 0x1111u;
                uint32_t p01 = ex2_f16x2(sd[0]) & prmt(y1, y2, sel);
                uint32_t p23 = ex2_f16x2(sd[1]) & prmt(z1, z2, sel);
                acc01 = hadd2(acc01, p01);
                acc23 = hadd2(acc23, p23);
                ap[nt >> 1][(nt & 1) * 2 + 0] = p01;
                ap[nt >> 1][(nt & 1) * 2 + 1] = p23;
            }
#pragma unroll
            for (int j = 0; j < 2; j++) {
                int kt = qd * 2 + j;
                uint32_t vb[4];
                uint32_t base = vb_base + (uint32_t)kt * (16 * 80) + v_lane_off;
                ldsm_x4_t(vb, base);
                mma_h(of[0], ap[j], vb);
                mma_h(of[1], ap[j], vb + 2);
                ldsm_x4_t(vb, base + 32);
                mma_h(of[2], ap[j], vb);
                mma_h(of[3], ap[j], vb + 2);
            }
        }
        {
            float2 f0 = h2_to_f2(acc01);
            float2 f1 = h2_to_f2(acc23);
            ls0 += f0.x + f0.y;
            ls1 += f1.x + f1.y;
        }
        __syncthreads();
    }

    ls0 += __shfl_xor_sync(0xFFFFFFFFu, ls0, 1);
    ls0 += __shfl_xor_sync(0xFFFFFFFFu, ls0, 2);
    ls1 += __shfl_xor_sync(0xFFFFFFFFu, ls1, 1);
    ls1 += __shfl_xor_sync(0xFFFFFFFFu, ls1, 2);

    // write partial O as raw f16x2 (values identical to prior fp32 path)
    uint32_t* p0 = g_pOh + (((size_t)z * NN * DD +
                             (size_t)row0 * DD + h * HD + 2 * tig) >> 1);
    uint32_t* p1 = p0 + 4 * DD;   // +8 rows (DD/2 uints per row)
#pragma unroll
    for (int v = 0; v < 4; v++) {
        p0[v * 4] = of[v][0];
        p1[v * 4] = of[v][1];
    }
    if (tig == 0) {
        g_pl[z * HH * NN + h * NN + row0] = ls0;
        g_pl[z * HH * NN + h * NN + row0 + 8] = ls1;
    }
}

// ================= combine split-KV partials -> bf16 attended =============
__global__ void __launch_bounds__(256) combine_kernel() {
    int i = (blockIdx.x * 256 + threadIdx.x) * 4;   // over NN*DD elements
    int n = i >> 8;            // DD = 256
    int c = i & 255;
    int h = c >> 5;
    float l = 0.f;
#pragma unroll
    for (int zz = 0; zz < NSPLIT; zz++)
        l += g_pl[zz * HH * NN + h * NN + n];
    float inv = 1.f / l;
    float ax = 0.f, ay = 0.f, az = 0.f, aw = 0.f;
#pragma unroll
    for (int zz = 0; zz < NSPLIT; zz++) {
        uint2 u = *(const uint2*)(g_pOh + (size_t)zz * (NN * DD / 2) + (i >> 1));
        float2 f0 = h2_to_f2(u.x);
        float2 f1 = h2_to_f2(u.y);
        ax += f0.x; ay += f0.y; az += f1.x; aw += f1.y;
    }
    *(uint2*)(g_attb + i) = make_uint2(
        pack_bf16x2(ax * inv, ay * inv),
        pack_bf16x2(az * inv, aw * inv));
}

// ================= fused Wo GEMM + residual + LayerNorm ====================
__global__ void __launch_bounds__(256) wo_ln_kernel(const float* __restrict__ bo,
                                                    const float* __restrict__ x,
                                                    const float* __restrict__ lnw,
                                                    const float* __restrict__ lnb,
                                                    float* __restrict__ out) {
    __shared__ __nv_bfloat16 sA[2][64 * 40];     // 2 x 5120 B
    __shared__ __nv_bfloat16 sB[2][32 * 264];    // 2 x 16896 B (528B rows)
    __shared__ float sW[256], sBb[256];
    __shared__ float s1buf[2][64], s2buf[2][64];

    const int tid = threadIdx.x;
    const int wid = tid >> 5;
    const int lane = tid & 31;
    const int m0 = blockIdx.x * 64;
    const int rgrp = wid & 3;
    const int cgrp = wid >> 2;

    const uint32_t aA = smem_u32(sA);
    const uint32_t aB = smem_u32(sB);
    const char* Abase = (const char*)g_attb + (size_t)m0 * (DD * 2);
    const char* Bbase = (const char*)(g_Wb + (size_t)3 * DD * DD);

    sW[tid] = lnw[tid];
    sBb[tid] = lnb[tid];

    {
        int r = tid >> 2, c = tid & 3;
        cp16(aA + r * 80 + c * 16, Abase + (size_t)r * 512 + c * 16);
#pragma unroll
        for (int j = 0; j < 4; j++) {
            int u = tid + j * 256;
            int br = u >> 5, bc = u & 31;
            cp16(aB + br * 528 + bc * 16, Bbase + (size_t)br * 512 + bc * 16);
        }
        CP_COMMIT();
    }

    float acc[16][4];
#pragma unroll
    for (int j = 0; j < 16; j++)
        acc[j][0] = acc[j][1] = acc[j][2] = acc[j][3] = 0.f;

    const int m = lane >> 3, rr = lane & 7;
    const uint32_t a_off = (uint32_t)((rgrp * 16 + (m & 1) * 8 + rr) * 80 + (m >> 1) * 16);
    const uint32_t b_lane = (uint32_t)(((lane >> 3) & 1) * 8 * 528 + (lane & 7) * 528 +
                                       (lane >> 4) * 16);

    for (int t = 0; t < 8; t++) {
        if (t < 7) {
            int nb = (t + 1) & 1;
            uint32_t dA = aA + (uint32_t)nb * 5120;
            uint32_t dB = aB + (uint32_t)nb * 16896;
            const char* As = Abase + (size_t)(t + 1) * 64;
            const char* Bs = Bbase + (size_t)(t + 1) * 32 * 512;
            {
                int r = tid >> 2, c = tid & 3;
                cp16(dA + r * 80 + c * 16, As + (size_t)r * 512 + c * 16);
            }
#pragma unroll
            for (int j = 0; j < 4; j++) {
                int u = tid + j * 256;
                int br = u >> 5, bc = u & 31;
                cp16(dB + br * 528 + bc * 16, Bs + (size_t)br * 512 + bc * 16);
            }
            CP_COMMIT();
            CP_WAIT(1);
        } else {
            CP_WAIT(0);
        }
        __syncthreads();

        const uint32_t bufA = aA + (uint32_t)(t & 1) * 5120;
        const uint32_t bufB = aB + (uint32_t)(t & 1) * 16896;

        uint32_t aq[2][4];
        ldsm_x4(aq[0], bufA + a_off);
        ldsm_x4(aq[1], bufA + a_off + 32);

#pragma unroll
        for (int ks = 0; ks < 2; ks++) {
#pragma unroll
            for (int j = 0; j < 8; j++) {
                uint32_t vb[4];
                ldsm_x4_t(vb, bufB + (uint32_t)(ks * 16 * 528 + cgrp * 256 + j * 32) + b_lane);
                mma_bf16(acc[2 * j],     aq[ks], vb);
                mma_bf16(acc[2 * j + 1], aq[ks], vb + 2);
            }
        }
        __syncthreads();
    }

    const int g = lane >> 2, tig = lane & 3;
    const int rloc0 = rgrp * 16 + g;
    const int rloc1 = rloc0 + 8;
    const int r0 = m0 + rloc0;
    float s1a = 0.f, s2a = 0.f, s1b = 0.f, s2b = 0.f;
#pragma unroll
    for (int j = 0; j < 16; j++) {
        int col = cgrp * 128 + j * 8 + 2 * tig;
        float2 b2 = __ldg((const float2*)(bo + col));
        float2 xa = __ldg((const float2*)(x + (size_t)r0 * DD + col));
        float2 xb = __ldg((const float2*)(x + (size_t)(r0 + 8) * DD + col));
        float v0 = acc[j][0] + b2.x + xa.x;
        float v1 = acc[j][1] + b2.y + xa.y;
        float v2 = acc[j][2] + b2.x + xb.x;
        float v3 = acc[j][3] + b2.y + xb.y;
        acc[j][0] = v0; acc[j][1] = v1; acc[j][2] = v2; acc[j][3] = v3;
        s1a += v0 + v1; s2a += v0 * v0 + v1 * v1;
        s1b += v2 + v3; s2b += v2 * v2 + v3 * v3;
    }
    s1a += __shfl_xor_sync(0xFFFFFFFFu, s1a, 1);
    s1a += __shfl_xor_sync(0xFFFFFFFFu, s1a, 2);
    s2a += __shfl_xor_sync(0xFFFFFFFFu, s2a, 1);
    s2a += __shfl_xor_sync(0xFFFFFFFFu, s2a, 2);
    s1b += __shfl_xor_sync(0xFFFFFFFFu, s1b, 1);
    s1b += __shfl_xor_sync(0xFFFFFFFFu, s1b, 2);
    s2b += __shfl_xor_sync(0xFFFFFFFFu, s2b, 1);
    s2b += __shfl_xor_sync(0xFFFFFFFFu, s2b, 2);
    if (tig == 0) {
        s1buf[cgrp][rloc0] = s1a; s2buf[cgrp][rloc0] = s2a;
        s1buf[cgrp][rloc1] = s1b; s2buf[cgrp][rloc1] = s2b;
    }
    __syncthreads();
    float mu0 = (s1buf[0][rloc0] + s1buf[1][rloc0]) * (1.f / 256.f);
    float va0 = (s2buf[0][rloc0] + s2buf[1][rloc0]) * (1.f / 256.f) - mu0 * mu0;
    float inv0 = rsqrtf(va0 + 1e-5f);
    float mu1 = (s1buf[0][rloc1] + s1buf[1][rloc1]) * (1.f / 256.f);
    float va1 = (s2buf[0][rloc1] + s2buf[1][rloc1]) * (1.f / 256.f) - mu1 * mu1;
    float inv1 = rsqrtf(va1 + 1e-5f);
#pragma unroll
    for (int j = 0; j < 16; j++) {
        int col = cgrp * 128 + j * 8 + 2 * tig;
        float w0 = sW[col], w1 = sW[col + 1];
        float c0 = sBb[col], c1 = sBb[col + 1];
        *(float2*)(out + (size_t)r0 * DD + col) =
            make_float2((acc[j][0] - mu0) * inv0 * w0 + c0,
                        (acc[j][1] - mu0) * inv0 * w1 + c1);
        *(float2*)(out + (size_t)(r0 + 8) * DD + col) =
            make_float2((acc[j][2] - mu1) * inv1 * w0 + c0,
                        (acc[j][3] - mu1) * inv1 * w1 + c1);
    }
}

// ================= launch =================
extern "C" void kernel_launch(void* const* d_in, const int* in_sizes, int n_in,
                              void* d_out, int out_size) {
    const float* x   = (const float*)d_in[0];
    const int*   ei  = (const int*)d_in[1];
    const float* Wq  = (const float*)d_in[2];
    const float* bq  = (const float*)d_in[3];
    const float* Wk  = (const float*)d_in[4];
    const float* bk  = (const float*)d_in[5];
    const float* Wv  = (const float*)d_in[6];
    const float* bv  = (const float*)d_in[7];
    const float* Wo  = (const float*)d_in[8];
    const float* bo  = (const float*)d_in[9];
    const float* lnw = (const float*)d_in[10];
    const float* lnb = (const float*)d_in[11];
    float* out = (float*)d_out;

    // K1: casts ∥ adjacency init
    k1_kernel<<<3328, 256>>>(x, Wq, Wk, Wv, Wo);
    // edge scatter
    edge_kernel<<<EE / 512, 128>>>(ei);
    // K3: QKV projections ∥ reach-2 mask
    k3_kernel<<<dim3(2, 64, 35), 128>>>(bq, bk, bv);
    // tensor-core attention, split-KV 4-way, 4 CTAs/SM
    attn_kernel<<<dim3(NN / 128, HH, NSPLIT), 256>>>();
    // combine partials (f16x2 -> fp32 sum -> bf16)
    combine_kernel<<<NN * DD / 1024, 256>>>();
    // fused Wo GEMM + residual + LayerNorm
    wo_ln_kernel<<<NN / 64, 256>>>(bo, x, lnw, lnb, out);
}